// round 11
// baseline (speedup 1.0000x reference)
#include <cuda_runtime.h>
#include <cuda_bf16.h>
#include <cstdint>

// Problem dims: B=256, T=256, D=96, H=6, E=16, DFF=384
#define NTOK 65536              // B*T

// ---------------- scratch (device globals; no allocations) ----------------
__device__ __nv_bfloat16 g_h [NTOK * 96];    // attn concat output (bf16)
__device__ __nv_bfloat16 g_q [NTOK * 96];    // [B*H, T, E] bf16
__device__ __nv_bfloat16 g_k [NTOK * 96];
__device__ __nv_bfloat16 g_v [NTOK * 96];

// pre-converted bf16 weights (k-major [k][n] layouts)
__device__ __nv_bfloat16 g_wq[96 * 96];
__device__ __nv_bfloat16 g_wk[96 * 96];
__device__ __nv_bfloat16 g_wv[96 * 96];
__device__ __nv_bfloat16 g_wp[96 * 96];
__device__ __nv_bfloat16 g_w1c[96 * 384];
__device__ __nv_bfloat16 g_w2c[384 * 96];

// ---------------- bf16 mma + ldmatrix + cp.async helpers ----------------
__device__ __forceinline__ void ldsm4(unsigned (&r)[4], unsigned addr) {
  asm volatile("ldmatrix.sync.aligned.m8n8.x4.shared.b16 {%0,%1,%2,%3}, [%4];"
               : "=r"(r[0]), "=r"(r[1]), "=r"(r[2]), "=r"(r[3]) : "r"(addr));
}
__device__ __forceinline__ void ldsm4t(unsigned (&r)[4], unsigned addr) {
  asm volatile("ldmatrix.sync.aligned.m8n8.x4.trans.shared.b16 {%0,%1,%2,%3}, [%4];"
               : "=r"(r[0]), "=r"(r[1]), "=r"(r[2]), "=r"(r[3]) : "r"(addr));
}
__device__ __forceinline__ void mma_bf16(float (&d)[4], const unsigned (&a)[4], unsigned b0, unsigned b1) {
  asm volatile("mma.sync.aligned.m16n8k16.row.col.f32.bf16.bf16.f32 "
               "{%0,%1,%2,%3}, {%4,%5,%6,%7}, {%8,%9}, {%0,%1,%2,%3};"
               : "+f"(d[0]), "+f"(d[1]), "+f"(d[2]), "+f"(d[3])
               : "r"(a[0]), "r"(a[1]), "r"(a[2]), "r"(a[3]), "r"(b0), "r"(b1));
}
__device__ __forceinline__ unsigned s2u(const void* p) {
  return (unsigned)__cvta_generic_to_shared(p);
}
__device__ __forceinline__ void cp16(unsigned dst, const void* src) {
  asm volatile("cp.async.cg.shared.global [%0], [%1], 16;" :: "r"(dst), "l"(src));
}
#define CP_COMMIT asm volatile("cp.async.commit_group;")
#define CP_WAIT(N) asm volatile("cp.async.wait_group %0;" :: "n"(N))
__device__ __forceinline__ unsigned pack_bf2(float lo, float hi) {
  __nv_bfloat162 h = __float22bfloat162_rn(make_float2(lo, hi));
  return *reinterpret_cast<unsigned*>(&h);
}

// ---------------- JAX threefry-2x32 (20 rounds) ----------------
__host__ __device__ __forceinline__ void tf2x32(unsigned k0, unsigned k1,
                                                unsigned x0, unsigned x1,
                                                unsigned &o0, unsigned &o1) {
  unsigned k2 = k0 ^ k1 ^ 0x1BD11BDAu;
  unsigned v0 = x0 + k0, v1 = x1 + k1;
#define TFR(r) { v0 += v1; v1 = (v1 << (r)) | (v1 >> (32 - (r))); v1 ^= v0; }
  TFR(13) TFR(15) TFR(26) TFR(6)   v0 += k1; v1 += k2 + 1u;
  TFR(17) TFR(29) TFR(16) TFR(24)  v0 += k2; v1 += k0 + 2u;
  TFR(13) TFR(15) TFR(26) TFR(6)   v0 += k0; v1 += k1 + 3u;
  TFR(17) TFR(29) TFR(16) TFR(24)  v0 += k1; v1 += k2 + 4u;
  TFR(13) TFR(15) TFR(26) TFR(6)   v0 += k2; v1 += k0 + 5u;
#undef TFR
  o0 = v0; o1 = v1;
}

__device__ __forceinline__ float jax_noise(unsigned k0, unsigned k1, unsigned idx) {
  unsigned o0, o1;
  tf2x32(k0, k1, 0u, idx, o0, o1);
  unsigned bits = o0 ^ o1;
  float u = __uint_as_float((bits >> 9) | 0x3f800000u) - 1.0f;
  const float lo = -0.99999994f;
  float val = u * 1.99999994f + lo;
  val = fmaxf(lo, val);
  return 0.1f * (1.4142135381698608f * erfinvf(val));
}

// ---------------- weight prep: fp32 -> bf16, gather into [k][n] ----------------
__global__ void __launch_bounds__(256) prep_kernel(const float* __restrict__ Wq,
                                                   const float* __restrict__ Wk,
                                                   const float* __restrict__ Wv,
                                                   const float* __restrict__ Wp,
                                                   const float* __restrict__ W1,
                                                   const float* __restrict__ W2) {
  int i = blockIdx.x * 256 + threadIdx.x;
  if (i < 9216) {
    int r = i / 96, c = i % 96;
    int h = c >> 4, e = c & 15;
    int s = h * 1536 + r * 16 + e;
    g_wq[i] = __float2bfloat16_rn(Wq[s]);
    g_wk[i] = __float2bfloat16_rn(Wk[s]);
    g_wv[i] = __float2bfloat16_rn(Wv[s]);
    g_wp[i] = __float2bfloat16_rn(Wp[i]);
  } else if (i < 9216 + 36864) {
    int j = i - 9216;
    g_w1c[j] = __float2bfloat16_rn(W1[j]);
  } else if (i < 9216 + 2 * 36864) {
    int j = i - 9216 - 36864;
    g_w2c[j] = __float2bfloat16_rn(W2[j]);
  }
}

// ============ smem geometry ============
// qkv kernel: stride 136 halves (68 words ≡ 4 mod 32)
#define SASTRIDE 136
#define A_ELEMS (128 * SASTRIDE)
#define B_ELEMS (96 * SASTRIDE)
#define SMEM_BYTES ((A_ELEMS + 2 * B_ELEMS) * 2)
// projff mega kernel: tighter strides
#define PASTR 104                 // 52 words ≡ 20 mod 32: 8-row ldsm walk distinct
#define PFSTR 392                 // 196 words ≡ 4 mod 32
#define PX1STR 100                // fp32 tile; <=2-way on float2 access
#define PF_A_ELEMS (128 * PASTR)
#define PF_F_ELEMS (128 * PFSTR)
#define PF_B_ELEMS (96 * PASTR)
#define PF_SMEM_BYTES ((PF_A_ELEMS + PF_F_ELEMS + 2 * PF_B_ELEMS) * 2 + 128 * PX1STR * 4)

// generic loaders (stride-parameterized)
#define CPA_B_S(BUF, SRC, LD, OFF, STR) \
  _Pragma("unroll") \
  for (int i_ = 0; i_ < 3; i_++) { \
    int c_ = tid + i_ * 384; int r_ = c_ / 12, q_ = c_ % 12; \
    cp16(s2u(&(BUF)[r_ * (STR) + q_ * 8]), (SRC) + r_ * (LD) + (OFF) + q_ * 8); \
  }
#define CPA_A_S(BUF, SRC, LD, OFF, STR) \
  _Pragma("unroll") \
  for (int i_ = 0; i_ < 4; i_++) { \
    int c_ = tid + i_ * 384; int r_ = c_ / 12, q_ = c_ % 12; \
    cp16(s2u(&(BUF)[r_ * (STR) + q_ * 8]), (SRC) + (size_t)(row0 + r_) * (LD) + (OFF) + q_ * 8); \
  }

// MMA over K=96: A frags from (AB0,AB1)+KOFF bytes; B tile BB with stride BSTR
#define MMA_K96_GEN(BB, AB0, AB1, KOFF, ACC, BSTR) \
  { \
    unsigned bb0 = s2u(&(BB)[lrow * (BSTR) + wc * 32 + lsel * 8]); \
    unsigned bb1 = bb0 + 16 * 2; \
    _Pragma("unroll") \
    for (int kc = 0; kc < 6; kc++) { \
      unsigned a[2][4], bt[2][4]; \
      ldsm4 (a[0],  (AB0) + (KOFF) + kc * 32); \
      ldsm4 (a[1],  (AB1) + (KOFF) + kc * 32); \
      ldsm4t(bt[0], bb0 + kc * (16 * (BSTR) * 2)); \
      ldsm4t(bt[1], bb1 + kc * (16 * (BSTR) * 2)); \
      _Pragma("unroll") \
      for (int mt = 0; mt < 2; mt++) \
        _Pragma("unroll") \
        for (int nt = 0; nt < 4; nt++) \
          mma_bf16(ACC[mt][nt], a[mt], bt[nt >> 1][(nt & 1) * 2], bt[nt >> 1][(nt & 1) * 2 + 1]); \
    } \
  }

// ---- fused LN1 + QKV: B tiles double-buffered; bf16 q/k/v out ----
__global__ void __launch_bounds__(384, 2) qkv_kernel(const float* __restrict__ x,
                                                     const float* __restrict__ ln1g,
                                                     const float* __restrict__ ln1b) {
  extern __shared__ __align__(16) char smraw[];
  __nv_bfloat16* sm_a  = reinterpret_cast<__nv_bfloat16*>(smraw);
  __nv_bfloat16* sm_b0 = sm_a + A_ELEMS;
  __nv_bfloat16* sm_b1 = sm_b0 + B_ELEMS;
  int tid = threadIdx.x;
  int warp = tid >> 5, lane = tid & 31;
  int wr = warp / 3, wc = warp % 3;
  int gid = lane >> 2, tig = lane & 3;
  int lrow = lane & 15, lsel = lane >> 4;
  int row0 = blockIdx.x * 128;
  unsigned aB0 = s2u(&sm_a[(wr * 32 + lrow) * SASTRIDE + lsel * 8]);
  unsigned aB1 = aB0 + 16 * SASTRIDE * 2;

  CPA_B_S(sm_b0, g_wq, 96, 0, SASTRIDE)
  CP_COMMIT;
  {
    float g0 = ln1g[lane], g1 = ln1g[lane + 32], g2 = ln1g[lane + 64];
    float b0 = ln1b[lane], b1 = ln1b[lane + 32], b2 = ln1b[lane + 64];
    for (int r = warp; r < 128; r += 12) {
      const float* xr = x + (size_t)(row0 + r) * 96;
      float v0 = xr[lane], v1 = xr[lane + 32], v2 = xr[lane + 64];
      float s = v0 + v1 + v2, sq = v0 * v0 + v1 * v1 + v2 * v2;
#pragma unroll
      for (int o = 16; o; o >>= 1) {
        s  += __shfl_xor_sync(0xffffffffu, s, o);
        sq += __shfl_xor_sync(0xffffffffu, sq, o);
      }
      float mu = s * (1.0f / 96.0f);
      float rs = rsqrtf(sq * (1.0f / 96.0f) - mu * mu + 1e-5f);
      sm_a[r * SASTRIDE + lane]      = __float2bfloat16_rn((v0 - mu) * rs * g0 + b0);
      sm_a[r * SASTRIDE + lane + 32] = __float2bfloat16_rn((v1 - mu) * rs * g1 + b1);
      sm_a[r * SASTRIDE + lane + 64] = __float2bfloat16_rn((v2 - mu) * rs * g2 + b2);
    }
  }
  for (int w = 0; w < 3; w++) {
    CP_WAIT(0);
    __syncthreads();
    if (w == 0) { CPA_B_S(sm_b1, g_wk, 96, 0, SASTRIDE) CP_COMMIT; }
    if (w == 1) { CPA_B_S(sm_b0, g_wv, 96, 0, SASTRIDE) CP_COMMIT; }
    float acc[2][4][4] = {};
    if (w & 1) { MMA_K96_GEN(sm_b1, aB0, aB1, 0, acc, SASTRIDE) }
    else       { MMA_K96_GEN(sm_b0, aB0, aB1, 0, acc, SASTRIDE) }
    __nv_bfloat16* Out = (w == 0) ? g_q : (w == 1) ? g_k : g_v;
#pragma unroll
    for (int mt = 0; mt < 2; mt++)
#pragma unroll
      for (int nt = 0; nt < 4; nt++) {
        int r0 = row0 + wr * 32 + mt * 16 + gid;
        int c0 = wc * 32 + nt * 8 + 2 * tig;
        int h = c0 >> 4, e = c0 & 15;
#pragma unroll
        for (int rr = 0; rr < 2; rr++) {
          int tok = r0 + rr * 8;
          int b_ = tok >> 8, t_ = tok & 255;
          *reinterpret_cast<__nv_bfloat162*>(&Out[((b_ * 6 + h) * 256 + t_) * 16 + e]) =
              __float22bfloat162_rn(make_float2(acc[mt][nt][2 * rr], acc[mt][nt][2 * rr + 1]));
        }
      }
  }
}

// ---- tensor-core flash attention (causal mask only on diagonal block) ----
__global__ void __launch_bounds__(256) attn_kernel() {
  int bh = blockIdx.x;
  __shared__ __align__(16) __nv_bfloat16 qs[256 * 24];
  __shared__ __align__(16) __nv_bfloat16 ks[256 * 24];
  __shared__ __align__(16) __nv_bfloat16 vs[256 * 24];
  const __nv_bfloat16* qb = g_q + (size_t)bh * 4096;
  const __nv_bfloat16* kb = g_k + (size_t)bh * 4096;
  const __nv_bfloat16* vb = g_v + (size_t)bh * 4096;
  int tid = threadIdx.x;
#pragma unroll
  for (int i = 0; i < 2; i++) {
    int idx = tid + i * 256;
    int r = idx >> 1, half = idx & 1;
    cp16(s2u(&qs[r * 24 + half * 8]), qb + r * 16 + half * 8);
    cp16(s2u(&ks[r * 24 + half * 8]), kb + r * 16 + half * 8);
    cp16(s2u(&vs[r * 24 + half * 8]), vb + r * 16 + half * 8);
  }
  CP_COMMIT;
  CP_WAIT(0);
  __syncthreads();
  int warp = tid >> 5, lane = tid & 31;
  int gid = lane >> 2, tig = lane & 3;
  int lrow = lane & 15, lsel = lane >> 4;
  int r0 = warp * 32;

  unsigned qa[2][4];
  ldsm4(qa[0], s2u(&qs[(r0 + lrow) * 24 + lsel * 8]));
  ldsm4(qa[1], s2u(&qs[(r0 + 16 + lrow) * 24 + lsel * 8]));

  float o[2][2][4] = {};
  float lsum[2][2] = {};
  int krow_off = (lane & 7) + ((lane >> 4) << 3);
  int khalf = (lane >> 3) & 1;
  int nkb = (r0 >> 6) + 1;

  for (int kbk = 0; kbk < nkb; kbk++) {
    int cb = kbk * 64;
    bool diag = (kbk == nkb - 1);
    unsigned kf[4][4];
#pragma unroll
    for (int i = 0; i < 4; i++)
      ldsm4(kf[i], s2u(&ks[(cb + i * 16 + krow_off) * 24 + khalf * 8]));
    unsigned pa[2][4][4];
#pragma unroll
    for (int mt = 0; mt < 2; mt++) {
      int ra = r0 + mt * 16 + gid, rb = ra + 8;
      float s[8][4];
#pragma unroll
      for (int nt = 0; nt < 8; nt++) {
        s[nt][0] = s[nt][1] = s[nt][2] = s[nt][3] = 0.0f;
        mma_bf16(s[nt], qa[mt], kf[nt >> 1][(nt & 1) * 2], kf[nt >> 1][(nt & 1) * 2 + 1]);
      }
      if (diag) {
#pragma unroll
        for (int nt = 0; nt < 8; nt++) {
          int c0 = cb + nt * 8 + 2 * tig;
          float p0 = (c0     <= ra) ? __expf(s[nt][0] * 0.25f) : 0.0f;
          float p1 = (c0 + 1 <= ra) ? __expf(s[nt][1] * 0.25f) : 0.0f;
          float p2 = (c0     <= rb) ? __expf(s[nt][2] * 0.25f) : 0.0f;
          float p3 = (c0 + 1 <= rb) ? __expf(s[nt][3] * 0.25f) : 0.0f;
          lsum[mt][0] += p0 + p1;
          lsum[mt][1] += p2 + p3;
          int kc = nt >> 1, hi = nt & 1;
          pa[mt][kc][hi * 2 + 0] = pack_bf2(p0, p1);
          pa[mt][kc][hi * 2 + 1] = pack_bf2(p2, p3);
        }
      } else {
#pragma unroll
        for (int nt = 0; nt < 8; nt++) {
          float p0 = __expf(s[nt][0] * 0.25f);
          float p1 = __expf(s[nt][1] * 0.25f);
          float p2 = __expf(s[nt][2] * 0.25f);
          float p3 = __expf(s[nt][3] * 0.25f);
          lsum[mt][0] += p0 + p1;
          lsum[mt][1] += p2 + p3;
          int kc = nt >> 1, hi = nt & 1;
          pa[mt][kc][hi * 2 + 0] = pack_bf2(p0, p1);
          pa[mt][kc][hi * 2 + 1] = pack_bf2(p2, p3);
        }
      }
    }
#pragma unroll
    for (int kc = 0; kc < 4; kc++) {
      unsigned vt[4];
      ldsm4t(vt, s2u(&vs[(cb + kc * 16 + lrow) * 24 + lsel * 8]));
#pragma unroll
      for (int mt = 0; mt < 2; mt++) {
        mma_bf16(o[mt][0], pa[mt][kc], vt[0], vt[1]);
        mma_bf16(o[mt][1], pa[mt][kc], vt[2], vt[3]);
      }
    }
  }
#pragma unroll
  for (int mt = 0; mt < 2; mt++)
#pragma unroll
    for (int rr = 0; rr < 2; rr++) {
      float v = lsum[mt][rr];
      v += __shfl_xor_sync(0xffffffffu, v, 1);
      v += __shfl_xor_sync(0xffffffffu, v, 2);
      lsum[mt][rr] = 1.0f / v;
    }
  int b_ = bh / 6, h_ = bh % 6;
#pragma unroll
  for (int mt = 0; mt < 2; mt++) {
    int ra = r0 + mt * 16 + gid, rb = ra + 8;
#pragma unroll
    for (int nt = 0; nt < 2; nt++) {
      int c = nt * 8 + 2 * tig;
      *reinterpret_cast<__nv_bfloat162*>(&g_h[((size_t)(b_ * 256 + ra)) * 96 + h_ * 16 + c]) =
          __float22bfloat162_rn(make_float2(o[mt][nt][0] * lsum[mt][0], o[mt][nt][1] * lsum[mt][0]));
      *reinterpret_cast<__nv_bfloat162*>(&g_h[((size_t)(b_ * 256 + rb)) * 96 + h_ * 16 + c]) =
          __float22bfloat162_rn(make_float2(o[mt][nt][2] * lsum[mt][1], o[mt][nt][3] * lsum[mt][1]));
    }
  }
}

// ---- MEGA: proj + residual + noise1 + LN2 + FF1 + FF2 + residual + noise2 ----
// x1 tile lives in smem fp32; never touches HBM.
__global__ void __launch_bounds__(384, 1) projff_kernel(const float* __restrict__ bp,
                                                        const float* __restrict__ x,
                                                        const float* __restrict__ b1,
                                                        const float* __restrict__ b2,
                                                        const float* __restrict__ ln2g,
                                                        const float* __restrict__ ln2b,
                                                        float* __restrict__ out,
                                                        unsigned n1k0, unsigned n1k1,
                                                        unsigned n2k0, unsigned n2k1) {
  extern __shared__ __align__(16) char smraw[];
  __nv_bfloat16* sm_a  = reinterpret_cast<__nv_bfloat16*>(smraw);
  __nv_bfloat16* sm_f  = sm_a + PF_A_ELEMS;
  __nv_bfloat16* sm_b0 = sm_f + PF_F_ELEMS;
  __nv_bfloat16* sm_b1 = sm_b0 + PF_B_ELEMS;
  float* sm_x1 = reinterpret_cast<float*>(sm_b1 + PF_B_ELEMS);
  int tid = threadIdx.x;
  int warp = tid >> 5, lane = tid & 31;
  int wr = warp / 3, wc = warp % 3;
  int gid = lane >> 2, tig = lane & 3;
  int lrow = lane & 15, lsel = lane >> 4;
  int row0 = blockIdx.x * 128;
  unsigned aB0 = s2u(&sm_a[(wr * 32 + lrow) * PASTR + lsel * 8]);
  unsigned aB1 = aB0 + 16 * PASTR * 2;
  unsigned fB0 = s2u(&sm_f[(wr * 32 + lrow) * PFSTR + lsel * 8]);
  unsigned fB1 = fB0 + 16 * PFSTR * 2;

  // --- stage 0: proj ---
  CPA_A_S(sm_a, g_h, 96, 0, PASTR)
  CPA_B_S(sm_b1, g_wp, 96, 0, PASTR)
  CP_COMMIT;

  // noise1 into registers while loads are in flight
  float2 n1[2][4][2];
#pragma unroll
  for (int mt = 0; mt < 2; mt++)
#pragma unroll
    for (int nt = 0; nt < 4; nt++) {
      int c0 = wc * 32 + nt * 8 + 2 * tig;
#pragma unroll
      for (int rr = 0; rr < 2; rr++) {
        unsigned i0 = (unsigned)((row0 + wr * 32 + mt * 16 + gid + rr * 8) * 96 + c0);
        n1[mt][nt][rr] = make_float2(jax_noise(n1k0, n1k1, i0),
                                     jax_noise(n1k0, n1k1, i0 + 1));
      }
    }

  CP_WAIT(0);
  __syncthreads();
  {
    float acc[2][4][4] = {};
    MMA_K96_GEN(sm_b1, aB0, aB1, 0, acc, PASTR)
    // prefetch W1 group 0 into sm_b0
    CPA_B_S(sm_b0, g_w1c, 384, 0, PASTR)
    CP_COMMIT;
    // x1 = x + proj + bp + noise1 -> smem fp32
#pragma unroll
    for (int mt = 0; mt < 2; mt++)
#pragma unroll
      for (int nt = 0; nt < 4; nt++) {
        int c0 = wc * 32 + nt * 8 + 2 * tig;
        float bp0 = bp[c0], bp1 = bp[c0 + 1];
#pragma unroll
        for (int rr = 0; rr < 2; rr++) {
          int rl = wr * 32 + mt * 16 + gid + rr * 8;
          int i0 = (row0 + rl) * 96 + c0;
          float2 xv = *reinterpret_cast<const float2*>(&x[i0]);
          *reinterpret_cast<float2*>(&sm_x1[rl * PX1STR + c0]) =
              make_float2(xv.x + acc[mt][nt][2 * rr]     + bp0 + n1[mt][nt][rr].x,
                          xv.y + acc[mt][nt][2 * rr + 1] + bp1 + n1[mt][nt][rr].y);
        }
      }
  }
  __syncthreads();

  // --- LN2: sm_x1 -> sm_a (bf16) ---
  {
    float g0 = ln2g[lane], g1 = ln2g[lane + 32], g2 = ln2g[lane + 64];
    float b0 = ln2b[lane], b1v = ln2b[lane + 32], b2v = ln2b[lane + 64];
    for (int r = warp; r < 128; r += 12) {
      const float* xr = &sm_x1[r * PX1STR];
      float v0 = xr[lane], v1 = xr[lane + 32], v2 = xr[lane + 64];
      float s = v0 + v1 + v2, sq = v0 * v0 + v1 * v1 + v2 * v2;
#pragma unroll
      for (int o = 16; o; o >>= 1) {
        s  += __shfl_xor_sync(0xffffffffu, s, o);
        sq += __shfl_xor_sync(0xffffffffu, sq, o);
      }
      float mu = s * (1.0f / 96.0f);
      float rs = rsqrtf(sq * (1.0f / 96.0f) - mu * mu + 1e-5f);
      sm_a[r * PASTR + lane]      = __float2bfloat16_rn((v0 - mu) * rs * g0 + b0);
      sm_a[r * PASTR + lane + 32] = __float2bfloat16_rn((v1 - mu) * rs * g1 + b1v);
      sm_a[r * PASTR + lane + 64] = __float2bfloat16_rn((v2 - mu) * rs * g2 + b2v);
    }
  }

  // --- FF1 (t=0..3) + FF2 (t=4..7), B tiles double-buffered ---
  float acc2[2][4][4] = {};
  for (int t = 0; t < 8; t++) {
    CP_WAIT(0);
    __syncthreads();
    if (t < 7) {
      int tn = t + 1;
      const __nv_bfloat16* src = (tn < 4) ? g_w1c : (g_w2c + (tn - 4) * 9216);
      int ld  = (tn < 4) ? 384 : 96;
      int off = (tn < 4) ? tn * 96 : 0;
      if (tn & 1) { CPA_B_S(sm_b1, src, ld, off, PASTR) } else { CPA_B_S(sm_b0, src, ld, off, PASTR) }
      CP_COMMIT;
    }
    if (t < 4) {
      float acc[2][4][4] = {};
      if (t & 1) { MMA_K96_GEN(sm_b1, aB0, aB1, 0, acc, PASTR) }
      else       { MMA_K96_GEN(sm_b0, aB0, aB1, 0, acc, PASTR) }
      int co = t * 96;
#pragma unroll
      for (int mt = 0; mt < 2; mt++)
#pragma unroll
        for (int nt = 0; nt < 4; nt++) {
          int c0 = wc * 32 + nt * 8 + 2 * tig;
          float bb0 = b1[co + c0], bb1 = b1[co + c0 + 1];
#pragma unroll
          for (int rr = 0; rr < 2; rr++) {
            int rl = wr * 32 + mt * 16 + gid + rr * 8;
            *reinterpret_cast<__nv_bfloat162*>(&sm_f[rl * PFSTR + co + c0]) =
                __float22bfloat162_rn(make_float2(fmaxf(acc[mt][nt][2 * rr] + bb0, 0.0f),
                                                  fmaxf(acc[mt][nt][2 * rr + 1] + bb1, 0.0f)));
          }
        }
    } else {
      int goff = (t - 4) * 192;   // byte offset into F rows (96 bf16)
      if (t & 1) { MMA_K96_GEN(sm_b1, fB0, fB1, goff, acc2, PASTR) }
      else       { MMA_K96_GEN(sm_b0, fB0, fB1, goff, acc2, PASTR) }
    }
  }

  // --- final epilogue: out = x1 + ff2 + b2 + noise2 ---
#pragma unroll
  for (int mt = 0; mt < 2; mt++)
#pragma unroll
    for (int nt = 0; nt < 4; nt++) {
      int c0 = wc * 32 + nt * 8 + 2 * tig;
      float bb0 = b2[c0], bb1 = b2[c0 + 1];
#pragma unroll
      for (int rr = 0; rr < 2; rr++) {
        int rl = wr * 32 + mt * 16 + gid + rr * 8;
        int i0 = (row0 + rl) * 96 + c0;
        float2 xv = *reinterpret_cast<const float2*>(&sm_x1[rl * PX1STR + c0]);
        *reinterpret_cast<float2*>(&out[i0]) =
            make_float2(xv.x + acc2[mt][nt][2 * rr]     + bb0 + jax_noise(n2k0, n2k1, (unsigned)i0),
                        xv.y + acc2[mt][nt][2 * rr + 1] + bb1 + jax_noise(n2k0, n2k1, (unsigned)(i0 + 1)));
      }
    }
}

extern "C" void kernel_launch(void* const* d_in, const int* in_sizes, int n_in,
                              void* d_out, int out_size) {
  (void)in_sizes; (void)n_in; (void)out_size;
  const float* x    = (const float*)d_in[0];
  const float* Wq   = (const float*)d_in[1];
  const float* Wk   = (const float*)d_in[2];
  const float* Wv   = (const float*)d_in[3];
  const float* Wp   = (const float*)d_in[4];
  const float* bp   = (const float*)d_in[5];
  const float* ln1g = (const float*)d_in[6];
  const float* ln1b = (const float*)d_in[7];
  const float* ln2g = (const float*)d_in[8];
  const float* ln2b = (const float*)d_in[9];
  const float* W1   = (const float*)d_in[10];
  const float* b1   = (const float*)d_in[11];
  const float* W2   = (const float*)d_in[12];
  const float* b2   = (const float*)d_in[13];
  float* out = (float*)d_out;

  unsigned nk1_0, nk1_1, nk2_0, nk2_1;
  tf2x32(0u, 42u, 0u, 0u, nk1_0, nk1_1);
  tf2x32(0u, 42u, 0u, 1u, nk2_0, nk2_1);

  cudaFuncSetAttribute(qkv_kernel,    cudaFuncAttributeMaxDynamicSharedMemorySize, SMEM_BYTES);
  cudaFuncSetAttribute(projff_kernel, cudaFuncAttributeMaxDynamicSharedMemorySize, PF_SMEM_BYTES);

  prep_kernel  <<<324, 256>>>(Wq, Wk, Wv, Wp, W1, W2);
  qkv_kernel   <<<512, 384, SMEM_BYTES>>>(x, ln1g, ln1b);
  attn_kernel  <<<1536, 256>>>();
  projff_kernel<<<512, 384, PF_SMEM_BYTES>>>(bp, x, b1, b2, ln2g, ln2b, out,
                                             nk1_0, nk1_1, nk2_0, nk2_1);
}

// round 12
// speedup vs baseline: 1.0453x; 1.0453x over previous
#include <cuda_runtime.h>
#include <cuda_bf16.h>
#include <cstdint>

// Problem dims: B=256, T=256, D=96, H=6, E=16, DFF=384
#define NTOK 65536              // B*T

// ---------------- scratch (device globals; no allocations) ----------------
__device__ __nv_bfloat16 g_h [NTOK * 96];    // attn concat output (bf16)
__device__ __nv_bfloat16 g_q [NTOK * 96];    // [B*H, T, E] bf16
__device__ __nv_bfloat16 g_k [NTOK * 96];
__device__ __nv_bfloat16 g_v [NTOK * 96];
__device__ float         g_x1[NTOK * 96];    // residual after attention branch

// pre-converted bf16 weights (k-major [k][n] layouts)
__device__ __nv_bfloat16 g_wq[96 * 96];
__device__ __nv_bfloat16 g_wk[96 * 96];
__device__ __nv_bfloat16 g_wv[96 * 96];
__device__ __nv_bfloat16 g_wp[96 * 96];
__device__ __nv_bfloat16 g_w1c[96 * 384];
__device__ __nv_bfloat16 g_w2c[384 * 96];

// ---------------- bf16 mma + ldmatrix + cp.async helpers ----------------
__device__ __forceinline__ void ldsm4(unsigned (&r)[4], unsigned addr) {
  asm volatile("ldmatrix.sync.aligned.m8n8.x4.shared.b16 {%0,%1,%2,%3}, [%4];"
               : "=r"(r[0]), "=r"(r[1]), "=r"(r[2]), "=r"(r[3]) : "r"(addr));
}
__device__ __forceinline__ void ldsm4t(unsigned (&r)[4], unsigned addr) {
  asm volatile("ldmatrix.sync.aligned.m8n8.x4.trans.shared.b16 {%0,%1,%2,%3}, [%4];"
               : "=r"(r[0]), "=r"(r[1]), "=r"(r[2]), "=r"(r[3]) : "r"(addr));
}
__device__ __forceinline__ void mma_bf16(float (&d)[4], const unsigned (&a)[4], unsigned b0, unsigned b1) {
  asm volatile("mma.sync.aligned.m16n8k16.row.col.f32.bf16.bf16.f32 "
               "{%0,%1,%2,%3}, {%4,%5,%6,%7}, {%8,%9}, {%0,%1,%2,%3};"
               : "+f"(d[0]), "+f"(d[1]), "+f"(d[2]), "+f"(d[3])
               : "r"(a[0]), "r"(a[1]), "r"(a[2]), "r"(a[3]), "r"(b0), "r"(b1));
}
__device__ __forceinline__ unsigned s2u(const void* p) {
  return (unsigned)__cvta_generic_to_shared(p);
}
__device__ __forceinline__ void cp16(unsigned dst, const void* src) {
  asm volatile("cp.async.cg.shared.global [%0], [%1], 16;" :: "r"(dst), "l"(src));
}
#define CP_COMMIT asm volatile("cp.async.commit_group;")
#define CP_WAIT(N) asm volatile("cp.async.wait_group %0;" :: "n"(N))
__device__ __forceinline__ unsigned pack_bf2(float lo, float hi) {
  __nv_bfloat162 h = __float22bfloat162_rn(make_float2(lo, hi));
  return *reinterpret_cast<unsigned*>(&h);
}

// ---------------- JAX threefry-2x32 (20 rounds) ----------------
__host__ __device__ __forceinline__ void tf2x32(unsigned k0, unsigned k1,
                                                unsigned x0, unsigned x1,
                                                unsigned &o0, unsigned &o1) {
  unsigned k2 = k0 ^ k1 ^ 0x1BD11BDAu;
  unsigned v0 = x0 + k0, v1 = x1 + k1;
#define TFR(r) { v0 += v1; v1 = (v1 << (r)) | (v1 >> (32 - (r))); v1 ^= v0; }
  TFR(13) TFR(15) TFR(26) TFR(6)   v0 += k1; v1 += k2 + 1u;
  TFR(17) TFR(29) TFR(16) TFR(24)  v0 += k2; v1 += k0 + 2u;
  TFR(13) TFR(15) TFR(26) TFR(6)   v0 += k0; v1 += k1 + 3u;
  TFR(17) TFR(29) TFR(16) TFR(24)  v0 += k1; v1 += k2 + 4u;
  TFR(13) TFR(15) TFR(26) TFR(6)   v0 += k2; v1 += k0 + 5u;
#undef TFR
  o0 = v0; o1 = v1;
}

__device__ __forceinline__ float jax_noise(unsigned k0, unsigned k1, unsigned idx) {
  unsigned o0, o1;
  tf2x32(k0, k1, 0u, idx, o0, o1);
  unsigned bits = o0 ^ o1;
  float u = __uint_as_float((bits >> 9) | 0x3f800000u) - 1.0f;
  const float lo = -0.99999994f;
  float val = u * 1.99999994f + lo;
  val = fmaxf(lo, val);
  return 0.1f * (1.4142135381698608f * erfinvf(val));
}

// ---------------- weight prep: fp32 -> bf16, gather into [k][n] ----------------
__global__ void __launch_bounds__(256) prep_kernel(const float* __restrict__ Wq,
                                                   const float* __restrict__ Wk,
                                                   const float* __restrict__ Wv,
                                                   const float* __restrict__ Wp,
                                                   const float* __restrict__ W1,
                                                   const float* __restrict__ W2) {
  int i = blockIdx.x * 256 + threadIdx.x;
  if (i < 9216) {
    int r = i / 96, c = i % 96;
    int h = c >> 4, e = c & 15;
    int s = h * 1536 + r * 16 + e;
    g_wq[i] = __float2bfloat16_rn(Wq[s]);
    g_wk[i] = __float2bfloat16_rn(Wk[s]);
    g_wv[i] = __float2bfloat16_rn(Wv[s]);
    g_wp[i] = __float2bfloat16_rn(Wp[i]);
  } else if (i < 9216 + 36864) {
    int j = i - 9216;
    g_w1c[j] = __float2bfloat16_rn(W1[j]);
  } else if (i < 9216 + 2 * 36864) {
    int j = i - 9216 - 36864;
    g_w2c[j] = __float2bfloat16_rn(W2[j]);
  }
}

// ============ smem geometry ============
#define SASTRIDE 136                     // 68 words ≡ 4 mod 32: conflict-free ldsm
#define FSTRIDE  392                     // 196 words ≡ 4 mod 32: conflict-free ldsm
#define A_ELEMS (128 * SASTRIDE)
#define B_ELEMS (96 * SASTRIDE)
#define F_ELEMS (128 * FSTRIDE)
#define SMEM_BYTES    ((A_ELEMS + 2 * B_ELEMS) * 2)
#define FF_SMEM_BYTES ((A_ELEMS + F_ELEMS + 2 * B_ELEMS) * 2)

#define GEMM_PROLOG \
  extern __shared__ __align__(16) char smraw[]; \
  __nv_bfloat16* sm_a  = reinterpret_cast<__nv_bfloat16*>(smraw); \
  __nv_bfloat16* sm_b0 = sm_a + A_ELEMS; \
  __nv_bfloat16* sm_b1 = sm_b0 + B_ELEMS; \
  int tid = threadIdx.x; \
  int warp = tid >> 5, lane = tid & 31; \
  int wr = warp / 3, wc = warp % 3; \
  int gid = lane >> 2, tig = lane & 3; \
  int lrow = lane & 15, lsel = lane >> 4; \
  int row0 = blockIdx.x * 128; \
  unsigned aB0 = s2u(&sm_a[(wr * 32 + lrow) * SASTRIDE + lsel * 8]); \
  unsigned aB1 = aB0 + 16 * SASTRIDE * 2;

#define CPA_B(BUF, SRC, LD, OFF) \
  _Pragma("unroll") \
  for (int i = 0; i < 3; i++) { \
    int c = tid + i * 384; int r = c / 12, q = c % 12; \
    cp16(s2u(&(BUF)[r * SASTRIDE + q * 8]), (SRC) + r * (LD) + (OFF) + q * 8); \
  }

#define CPA_A(SRC, LD, OFF) \
  _Pragma("unroll") \
  for (int i = 0; i < 4; i++) { \
    int c = tid + i * 384; int r = c / 12, q = c % 12; \
    cp16(s2u(&sm_a[r * SASTRIDE + q * 8]), (SRC) + (size_t)(row0 + r) * (LD) + (OFF) + q * 8); \
  }

// 768-thread variants for the ff kernel
#define CPA_B_768(BUF, SRC, LD, OFF) \
  _Pragma("unroll") \
  for (int i = 0; i < 2; i++) { \
    int c = tid + i * 768; \
    if (c < 1152) { \
      int r = c / 12, q = c % 12; \
      cp16(s2u(&(BUF)[r * SASTRIDE + q * 8]), (SRC) + r * (LD) + (OFF) + q * 8); \
    } \
  }

#define LN_TO_SMEM(SRC, G, Bv, NW) \
  { \
    float g0 = (G)[lane], g1 = (G)[lane + 32], g2 = (G)[lane + 64]; \
    float b0 = (Bv)[lane], b1 = (Bv)[lane + 32], b2 = (Bv)[lane + 64]; \
    for (int r = warp; r < 128; r += (NW)) { \
      const float* xr = (SRC) + (size_t)(row0 + r) * 96; \
      float v0 = xr[lane], v1 = xr[lane + 32], v2 = xr[lane + 64]; \
      float s = v0 + v1 + v2, sq = v0 * v0 + v1 * v1 + v2 * v2; \
      _Pragma("unroll") \
      for (int o = 16; o; o >>= 1) { \
        s  += __shfl_xor_sync(0xffffffffu, s, o); \
        sq += __shfl_xor_sync(0xffffffffu, sq, o); \
      } \
      float mu = s * (1.0f / 96.0f); \
      float rs = rsqrtf(sq * (1.0f / 96.0f) - mu * mu + 1e-5f); \
      sm_a[r * SASTRIDE + lane]      = __float2bfloat16_rn((v0 - mu) * rs * g0 + b0); \
      sm_a[r * SASTRIDE + lane + 32] = __float2bfloat16_rn((v1 - mu) * rs * g1 + b1); \
      sm_a[r * SASTRIDE + lane + 64] = __float2bfloat16_rn((v2 - mu) * rs * g2 + b2); \
    } \
  }

// MMA over K=96 (12-warp layout): A frags from (AB0,AB1)+KOFF, B tile BB
#define MMA_K96_GEN(BB, AB0, AB1, KOFF, ACC) \
  { \
    unsigned bb0 = s2u(&(BB)[lrow * SASTRIDE + wc * 32 + lsel * 8]); \
    unsigned bb1 = bb0 + 16 * 2; \
    _Pragma("unroll") \
    for (int kc = 0; kc < 6; kc++) { \
      unsigned a[2][4], bt[2][4]; \
      ldsm4 (a[0],  (AB0) + (KOFF) + kc * 32); \
      ldsm4 (a[1],  (AB1) + (KOFF) + kc * 32); \
      ldsm4t(bt[0], bb0 + kc * (16 * SASTRIDE * 2)); \
      ldsm4t(bt[1], bb1 + kc * (16 * SASTRIDE * 2)); \
      _Pragma("unroll") \
      for (int mt = 0; mt < 2; mt++) \
        _Pragma("unroll") \
        for (int nt = 0; nt < 4; nt++) \
          mma_bf16(ACC[mt][nt], a[mt], bt[nt >> 1][(nt & 1) * 2], bt[nt >> 1][(nt & 1) * 2 + 1]); \
    } \
  }
#define MMA_K96_BF16(BB) MMA_K96_GEN(BB, aB0, aB1, 0, acc)

// MMA over K=96 (24-warp layout, warp tile 32x16): acc[2][2][4]
#define MMA_K96_768(BB, AB0, AB1, KOFF, ACC) \
  { \
    unsigned bb0 = s2u(&(BB)[lrow * SASTRIDE + wc6 * 16 + lsel * 8]); \
    _Pragma("unroll") \
    for (int kc = 0; kc < 6; kc++) { \
      unsigned a[2][4], bt[4]; \
      ldsm4 (a[0],  (AB0) + (KOFF) + kc * 32); \
      ldsm4 (a[1],  (AB1) + (KOFF) + kc * 32); \
      ldsm4t(bt,    bb0 + kc * (16 * SASTRIDE * 2)); \
      _Pragma("unroll") \
      for (int mt = 0; mt < 2; mt++) \
        _Pragma("unroll") \
        for (int nt = 0; nt < 2; nt++) \
          mma_bf16(ACC[mt][nt], a[mt], bt[nt * 2], bt[nt * 2 + 1]); \
    } \
  }

// ---- fused LN1 + QKV: B tiles double-buffered; bf16 q/k/v out ----
__global__ void __launch_bounds__(384, 2) qkv_kernel(const float* __restrict__ x,
                                                     const float* __restrict__ ln1g,
                                                     const float* __restrict__ ln1b) {
  GEMM_PROLOG
  CPA_B(sm_b0, g_wq, 96, 0)
  CP_COMMIT;
  LN_TO_SMEM(x, ln1g, ln1b, 12)
  for (int w = 0; w < 3; w++) {
    CP_WAIT(0);
    __syncthreads();
    if (w == 0) { CPA_B(sm_b1, g_wk, 96, 0) CP_COMMIT; }
    if (w == 1) { CPA_B(sm_b0, g_wv, 96, 0) CP_COMMIT; }
    float acc[2][4][4] = {};
    if (w & 1) { MMA_K96_BF16(sm_b1) } else { MMA_K96_BF16(sm_b0) }
    __nv_bfloat16* Out = (w == 0) ? g_q : (w == 1) ? g_k : g_v;
#pragma unroll
    for (int mt = 0; mt < 2; mt++)
#pragma unroll
      for (int nt = 0; nt < 4; nt++) {
        int r0 = row0 + wr * 32 + mt * 16 + gid;
        int c0 = wc * 32 + nt * 8 + 2 * tig;
        int h = c0 >> 4, e = c0 & 15;
#pragma unroll
        for (int rr = 0; rr < 2; rr++) {
          int tok = r0 + rr * 8;
          int b_ = tok >> 8, t_ = tok & 255;
          *reinterpret_cast<__nv_bfloat162*>(&Out[((b_ * 6 + h) * 256 + t_) * 16 + e]) =
              __float22bfloat162_rn(make_float2(acc[mt][nt][2 * rr], acc[mt][nt][2 * rr + 1]));
        }
      }
  }
}

// ---- tensor-core flash attention (causal mask only on diagonal block) ----
__global__ void __launch_bounds__(256) attn_kernel() {
  int bh = blockIdx.x;
  __shared__ __align__(16) __nv_bfloat16 qs[256 * 24];
  __shared__ __align__(16) __nv_bfloat16 ks[256 * 24];
  __shared__ __align__(16) __nv_bfloat16 vs[256 * 24];
  const __nv_bfloat16* qb = g_q + (size_t)bh * 4096;
  const __nv_bfloat16* kb = g_k + (size_t)bh * 4096;
  const __nv_bfloat16* vb = g_v + (size_t)bh * 4096;
  int tid = threadIdx.x;
#pragma unroll
  for (int i = 0; i < 2; i++) {
    int idx = tid + i * 256;
    int r = idx >> 1, half = idx & 1;
    cp16(s2u(&qs[r * 24 + half * 8]), qb + r * 16 + half * 8);
    cp16(s2u(&ks[r * 24 + half * 8]), kb + r * 16 + half * 8);
    cp16(s2u(&vs[r * 24 + half * 8]), vb + r * 16 + half * 8);
  }
  CP_COMMIT;
  CP_WAIT(0);
  __syncthreads();
  int warp = tid >> 5, lane = tid & 31;
  int gid = lane >> 2, tig = lane & 3;
  int lrow = lane & 15, lsel = lane >> 4;
  int r0 = warp * 32;

  unsigned qa[2][4];
  ldsm4(qa[0], s2u(&qs[(r0 + lrow) * 24 + lsel * 8]));
  ldsm4(qa[1], s2u(&qs[(r0 + 16 + lrow) * 24 + lsel * 8]));

  float o[2][2][4] = {};
  float lsum[2][2] = {};
  int krow_off = (lane & 7) + ((lane >> 4) << 3);
  int khalf = (lane >> 3) & 1;
  int nkb = (r0 >> 6) + 1;

  for (int kbk = 0; kbk < nkb; kbk++) {
    int cb = kbk * 64;
    bool diag = (kbk == nkb - 1);
    unsigned kf[4][4];
#pragma unroll
    for (int i = 0; i < 4; i++)
      ldsm4(kf[i], s2u(&ks[(cb + i * 16 + krow_off) * 24 + khalf * 8]));
    unsigned pa[2][4][4];
#pragma unroll
    for (int mt = 0; mt < 2; mt++) {
      int ra = r0 + mt * 16 + gid, rb = ra + 8;
      float s[8][4];
#pragma unroll
      for (int nt = 0; nt < 8; nt++) {
        s[nt][0] = s[nt][1] = s[nt][2] = s[nt][3] = 0.0f;
        mma_bf16(s[nt], qa[mt], kf[nt >> 1][(nt & 1) * 2], kf[nt >> 1][(nt & 1) * 2 + 1]);
      }
      if (diag) {
#pragma unroll
        for (int nt = 0; nt < 8; nt++) {
          int c0 = cb + nt * 8 + 2 * tig;
          float p0 = (c0     <= ra) ? __expf(s[nt][0] * 0.25f) : 0.0f;
          float p1 = (c0 + 1 <= ra) ? __expf(s[nt][1] * 0.25f) : 0.0f;
          float p2 = (c0     <= rb) ? __expf(s[nt][2] * 0.25f) : 0.0f;
          float p3 = (c0 + 1 <= rb) ? __expf(s[nt][3] * 0.25f) : 0.0f;
          lsum[mt][0] += p0 + p1;
          lsum[mt][1] += p2 + p3;
          int kc = nt >> 1, hi = nt & 1;
          pa[mt][kc][hi * 2 + 0] = pack_bf2(p0, p1);
          pa[mt][kc][hi * 2 + 1] = pack_bf2(p2, p3);
        }
      } else {
#pragma unroll
        for (int nt = 0; nt < 8; nt++) {
          float p0 = __expf(s[nt][0] * 0.25f);
          float p1 = __expf(s[nt][1] * 0.25f);
          float p2 = __expf(s[nt][2] * 0.25f);
          float p3 = __expf(s[nt][3] * 0.25f);
          lsum[mt][0] += p0 + p1;
          lsum[mt][1] += p2 + p3;
          int kc = nt >> 1, hi = nt & 1;
          pa[mt][kc][hi * 2 + 0] = pack_bf2(p0, p1);
          pa[mt][kc][hi * 2 + 1] = pack_bf2(p2, p3);
        }
      }
    }
#pragma unroll
    for (int kc = 0; kc < 4; kc++) {
      unsigned vt[4];
      ldsm4t(vt, s2u(&vs[(cb + kc * 16 + lrow) * 24 + lsel * 8]));
#pragma unroll
      for (int mt = 0; mt < 2; mt++) {
        mma_bf16(o[mt][0], pa[mt][kc], vt[0], vt[1]);
        mma_bf16(o[mt][1], pa[mt][kc], vt[2], vt[3]);
      }
    }
  }
#pragma unroll
  for (int mt = 0; mt < 2; mt++)
#pragma unroll
    for (int rr = 0; rr < 2; rr++) {
      float v = lsum[mt][rr];
      v += __shfl_xor_sync(0xffffffffu, v, 1);
      v += __shfl_xor_sync(0xffffffffu, v, 2);
      lsum[mt][rr] = 1.0f / v;
    }
  int b_ = bh / 6, h_ = bh % 6;
#pragma unroll
  for (int mt = 0; mt < 2; mt++) {
    int ra = r0 + mt * 16 + gid, rb = ra + 8;
#pragma unroll
    for (int nt = 0; nt < 2; nt++) {
      int c = nt * 8 + 2 * tig;
      *reinterpret_cast<__nv_bfloat162*>(&g_h[((size_t)(b_ * 256 + ra)) * 96 + h_ * 16 + c]) =
          __float22bfloat162_rn(make_float2(o[mt][nt][0] * lsum[mt][0], o[mt][nt][1] * lsum[mt][0]));
      *reinterpret_cast<__nv_bfloat162*>(&g_h[((size_t)(b_ * 256 + rb)) * 96 + h_ * 16 + c]) =
          __float22bfloat162_rn(make_float2(o[mt][nt][2] * lsum[mt][1], o[mt][nt][3] * lsum[mt][1]));
    }
  }
}

// ---- projection + residual + noise1 (fused epilogue) ----
__global__ void __launch_bounds__(384, 2) proj_kernel(const float* __restrict__ bp,
                                                      const float* __restrict__ x,
                                                      unsigned nk0, unsigned nk1v) {
  GEMM_PROLOG
  CPA_A(g_h, 96, 0)
  CPA_B(sm_b0, g_wp, 96, 0)
  CP_COMMIT;
  CP_WAIT(0);
  __syncthreads();
  float acc[2][4][4] = {};
  MMA_K96_BF16(sm_b0)
#pragma unroll
  for (int mt = 0; mt < 2; mt++)
#pragma unroll
    for (int nt = 0; nt < 4; nt++) {
      int r0 = row0 + wr * 32 + mt * 16 + gid;
      int c0 = wc * 32 + nt * 8 + 2 * tig;
      float bp0 = bp[c0], bp1 = bp[c0 + 1];
#pragma unroll
      for (int rr = 0; rr < 2; rr++) {
        int i0 = (r0 + rr * 8) * 96 + c0;
        float2 xv = *reinterpret_cast<const float2*>(&x[i0]);
        *reinterpret_cast<float2*>(&g_x1[i0]) =
            make_float2(xv.x + acc[mt][nt][2 * rr]     + bp0 + jax_noise(nk0, nk1v, (unsigned)i0),
                        xv.y + acc[mt][nt][2 * rr + 1] + bp1 + jax_noise(nk0, nk1v, (unsigned)(i0 + 1)));
      }
    }
}

// ---- fused LN2 + FF1 + FF2 + residual + noise2 -> out (768 threads / 24 warps) ----
// F tile (128x384 bf16) lives in smem; 8 B tiles stream through a double buffer.
// Warp tile 32 rows x 16 cols: wr6 = warp/6 (4 row groups), wc6 = warp%6 (6 col groups).
__global__ void __launch_bounds__(768, 1) ff_kernel(const float* __restrict__ b1,
                                                    const float* __restrict__ b2,
                                                    const float* __restrict__ ln2g,
                                                    const float* __restrict__ ln2b,
                                                    float* __restrict__ out,
                                                    unsigned nk0, unsigned nk1v) {
  extern __shared__ __align__(16) char smraw[];
  __nv_bfloat16* sm_a  = reinterpret_cast<__nv_bfloat16*>(smraw);
  __nv_bfloat16* sm_f  = sm_a + A_ELEMS;
  __nv_bfloat16* sm_b0 = sm_f + F_ELEMS;
  __nv_bfloat16* sm_b1 = sm_b0 + B_ELEMS;
  int tid = threadIdx.x;
  int warp = tid >> 5, lane = tid & 31;
  int wr6 = warp / 6, wc6 = warp % 6;
  int gid = lane >> 2, tig = lane & 3;
  int lrow = lane & 15, lsel = lane >> 4;
  int row0 = blockIdx.x * 128;
  unsigned aB0 = s2u(&sm_a[(wr6 * 32 + lrow) * SASTRIDE + lsel * 8]);
  unsigned aB1 = aB0 + 16 * SASTRIDE * 2;
  unsigned fB0 = s2u(&sm_f[(wr6 * 32 + lrow) * FSTRIDE + lsel * 8]);
  unsigned fB1 = fB0 + 16 * FSTRIDE * 2;

  CPA_B_768(sm_b0, g_w1c, 384, 0)
  CP_COMMIT;
  LN_TO_SMEM(g_x1, ln2g, ln2b, 24)

  float acc2[2][2][4] = {};
  for (int t = 0; t < 8; t++) {
    CP_WAIT(0);
    __syncthreads();
    if (t < 7) {
      int tn = t + 1;
      const __nv_bfloat16* src = (tn < 4) ? g_w1c : (g_w2c + (tn - 4) * 9216);
      int ld  = (tn < 4) ? 384 : 96;
      int off = (tn < 4) ? tn * 96 : 0;
      if (tn & 1) { CPA_B_768(sm_b1, src, ld, off) } else { CPA_B_768(sm_b0, src, ld, off) }
      CP_COMMIT;
    }
    if (t < 4) {
      // FF1 group t: A(sm_a) x W1[:, t*96 : t*96+96] -> relu -> sm_f
      float acc[2][2][4] = {};
      if (t & 1) { MMA_K96_768(sm_b1, aB0, aB1, 0, acc) }
      else       { MMA_K96_768(sm_b0, aB0, aB1, 0, acc) }
      int co = t * 96;
#pragma unroll
      for (int mt = 0; mt < 2; mt++)
#pragma unroll
        for (int nt = 0; nt < 2; nt++) {
          int c0 = wc6 * 16 + nt * 8 + 2 * tig;
          float bb0 = b1[co + c0], bb1 = b1[co + c0 + 1];
#pragma unroll
          for (int rr = 0; rr < 2; rr++) {
            int rl = wr6 * 32 + mt * 16 + gid + rr * 8;
            *reinterpret_cast<__nv_bfloat162*>(&sm_f[rl * FSTRIDE + co + c0]) =
                __float22bfloat162_rn(make_float2(fmaxf(acc[mt][nt][2 * rr] + bb0, 0.0f),
                                                  fmaxf(acc[mt][nt][2 * rr + 1] + bb1, 0.0f)));
          }
        }
    } else {
      // FF2 chunk t-4: F[:, g*96 : g*96+96] x W2[g*96 : g*96+96, :] accumulate
      int goff = (t - 4) * 192;   // byte offset into F rows (96 bf16)
      if (t & 1) { MMA_K96_768(sm_b1, fB0, fB1, goff, acc2) }
      else       { MMA_K96_768(sm_b0, fB0, fB1, goff, acc2) }
    }
  }
#pragma unroll
  for (int mt = 0; mt < 2; mt++)
#pragma unroll
    for (int nt = 0; nt < 2; nt++) {
      int r0 = row0 + wr6 * 32 + mt * 16 + gid;
      int c0 = wc6 * 16 + nt * 8 + 2 * tig;
      float bb0 = b2[c0], bb1 = b2[c0 + 1];
#pragma unroll
      for (int rr = 0; rr < 2; rr++) {
        int i0 = (r0 + rr * 8) * 96 + c0;
        float2 xv = *reinterpret_cast<const float2*>(&g_x1[i0]);
        *reinterpret_cast<float2*>(&out[i0]) =
            make_float2(xv.x + acc2[mt][nt][2 * rr]     + bb0 + jax_noise(nk0, nk1v, (unsigned)i0),
                        xv.y + acc2[mt][nt][2 * rr + 1] + bb1 + jax_noise(nk0, nk1v, (unsigned)(i0 + 1)));
      }
    }
}

extern "C" void kernel_launch(void* const* d_in, const int* in_sizes, int n_in,
                              void* d_out, int out_size) {
  (void)in_sizes; (void)n_in; (void)out_size;
  const float* x    = (const float*)d_in[0];
  const float* Wq   = (const float*)d_in[1];
  const float* Wk   = (const float*)d_in[2];
  const float* Wv   = (const float*)d_in[3];
  const float* Wp   = (const float*)d_in[4];
  const float* bp   = (const float*)d_in[5];
  const float* ln1g = (const float*)d_in[6];
  const float* ln1b = (const float*)d_in[7];
  const float* ln2g = (const float*)d_in[8];
  const float* ln2b = (const float*)d_in[9];
  const float* W1   = (const float*)d_in[10];
  const float* b1   = (const float*)d_in[11];
  const float* W2   = (const float*)d_in[12];
  const float* b2   = (const float*)d_in[13];
  float* out = (float*)d_out;

  unsigned nk1_0, nk1_1, nk2_0, nk2_1;
  tf2x32(0u, 42u, 0u, 0u, nk1_0, nk1_1);
  tf2x32(0u, 42u, 0u, 1u, nk2_0, nk2_1);

  cudaFuncSetAttribute(qkv_kernel,  cudaFuncAttributeMaxDynamicSharedMemorySize, SMEM_BYTES);
  cudaFuncSetAttribute(proj_kernel, cudaFuncAttributeMaxDynamicSharedMemorySize, SMEM_BYTES);
  cudaFuncSetAttribute(ff_kernel,   cudaFuncAttributeMaxDynamicSharedMemorySize, FF_SMEM_BYTES);

  prep_kernel<<<324, 256>>>(Wq, Wk, Wv, Wp, W1, W2);
  qkv_kernel <<<512, 384, SMEM_BYTES>>>(x, ln1g, ln1b);
  attn_kernel<<<1536, 256>>>();
  proj_kernel<<<512, 384, SMEM_BYTES>>>(bp, x, nk1_0, nk1_1);
  ff_kernel  <<<512, 768, FF_SMEM_BYTES>>>(b1, b2, ln2g, ln2b, out, nk2_0, nk2_1);
}

// round 13
// speedup vs baseline: 1.1105x; 1.0624x over previous
#include <cuda_runtime.h>
#include <cuda_bf16.h>
#include <cstdint>

// Problem dims: B=256, T=256, D=96, H=6, E=16, DFF=384
#define NTOK 65536              // B*T

// ---------------- scratch (device globals; no allocations) ----------------
__device__ float g_x1[NTOK * 96];            // residual after attention branch

// pre-converted bf16 weights (k-major [k][n] layouts)
__device__ __nv_bfloat16 g_wq[96 * 96];
__device__ __nv_bfloat16 g_wk[96 * 96];
__device__ __nv_bfloat16 g_wv[96 * 96];
__device__ __nv_bfloat16 g_wp[96 * 96];
__device__ __nv_bfloat16 g_w1c[96 * 384];
__device__ __nv_bfloat16 g_w2c[384 * 96];

// ---------------- bf16 mma + ldmatrix + cp.async helpers ----------------
__device__ __forceinline__ void ldsm4(unsigned (&r)[4], unsigned addr) {
  asm volatile("ldmatrix.sync.aligned.m8n8.x4.shared.b16 {%0,%1,%2,%3}, [%4];"
               : "=r"(r[0]), "=r"(r[1]), "=r"(r[2]), "=r"(r[3]) : "r"(addr));
}
__device__ __forceinline__ void ldsm4t(unsigned (&r)[4], unsigned addr) {
  asm volatile("ldmatrix.sync.aligned.m8n8.x4.trans.shared.b16 {%0,%1,%2,%3}, [%4];"
               : "=r"(r[0]), "=r"(r[1]), "=r"(r[2]), "=r"(r[3]) : "r"(addr));
}
__device__ __forceinline__ void mma_bf16(float (&d)[4], const unsigned (&a)[4], unsigned b0, unsigned b1) {
  asm volatile("mma.sync.aligned.m16n8k16.row.col.f32.bf16.bf16.f32 "
               "{%0,%1,%2,%3}, {%4,%5,%6,%7}, {%8,%9}, {%0,%1,%2,%3};"
               : "+f"(d[0]), "+f"(d[1]), "+f"(d[2]), "+f"(d[3])
               : "r"(a[0]), "r"(a[1]), "r"(a[2]), "r"(a[3]), "r"(b0), "r"(b1));
}
__device__ __forceinline__ unsigned s2u(const void* p) {
  return (unsigned)__cvta_generic_to_shared(p);
}
__device__ __forceinline__ void cp16(unsigned dst, const void* src) {
  asm volatile("cp.async.cg.shared.global [%0], [%1], 16;" :: "r"(dst), "l"(src));
}
#define CP_COMMIT asm volatile("cp.async.commit_group;")
#define CP_WAIT(N) asm volatile("cp.async.wait_group %0;" :: "n"(N))
__device__ __forceinline__ unsigned pack_bf2(float lo, float hi) {
  __nv_bfloat162 h = __float22bfloat162_rn(make_float2(lo, hi));
  return *reinterpret_cast<unsigned*>(&h);
}

// ---------------- JAX threefry-2x32 (20 rounds) ----------------
__host__ __device__ __forceinline__ void tf2x32(unsigned k0, unsigned k1,
                                                unsigned x0, unsigned x1,
                                                unsigned &o0, unsigned &o1) {
  unsigned k2 = k0 ^ k1 ^ 0x1BD11BDAu;
  unsigned v0 = x0 + k0, v1 = x1 + k1;
#define TFR(r) { v0 += v1; v1 = (v1 << (r)) | (v1 >> (32 - (r))); v1 ^= v0; }
  TFR(13) TFR(15) TFR(26) TFR(6)   v0 += k1; v1 += k2 + 1u;
  TFR(17) TFR(29) TFR(16) TFR(24)  v0 += k2; v1 += k0 + 2u;
  TFR(13) TFR(15) TFR(26) TFR(6)   v0 += k0; v1 += k1 + 3u;
  TFR(17) TFR(29) TFR(16) TFR(24)  v0 += k1; v1 += k2 + 4u;
  TFR(13) TFR(15) TFR(26) TFR(6)   v0 += k2; v1 += k0 + 5u;
#undef TFR
  o0 = v0; o1 = v1;
}

__device__ __forceinline__ float jax_noise(unsigned k0, unsigned k1, unsigned idx) {
  unsigned o0, o1;
  tf2x32(k0, k1, 0u, idx, o0, o1);
  unsigned bits = o0 ^ o1;
  float u = __uint_as_float((bits >> 9) | 0x3f800000u) - 1.0f;
  const float lo = -0.99999994f;
  float val = u * 1.99999994f + lo;
  val = fmaxf(lo, val);
  return 0.1f * (1.4142135381698608f * erfinvf(val));
}

// ---------------- weight prep: fp32 -> bf16, gather into [k][n] ----------------
__global__ void __launch_bounds__(256) prep_kernel(const float* __restrict__ Wq,
                                                   const float* __restrict__ Wk,
                                                   const float* __restrict__ Wv,
                                                   const float* __restrict__ Wp,
                                                   const float* __restrict__ W1,
                                                   const float* __restrict__ W2) {
  int i = blockIdx.x * 256 + threadIdx.x;
  if (i < 9216) {
    int r = i / 96, c = i % 96;
    int h = c >> 4, e = c & 15;
    int s = h * 1536 + r * 16 + e;
    g_wq[i] = __float2bfloat16_rn(Wq[s]);
    g_wk[i] = __float2bfloat16_rn(Wk[s]);
    g_wv[i] = __float2bfloat16_rn(Wv[s]);
    g_wp[i] = __float2bfloat16_rn(Wp[i]);
  } else if (i < 9216 + 36864) {
    int j = i - 9216;
    g_w1c[j] = __float2bfloat16_rn(W1[j]);
  } else if (i < 9216 + 2 * 36864) {
    int j = i - 9216 - 36864;
    g_w2c[j] = __float2bfloat16_rn(W2[j]);
  }
}

// ============ qkv+attn+proj mega kernel geometry ============
#define QSTR 104                 // 52 words, /4 = 13 (odd) -> conflict-free ldsm phases
#define QX_ELEMS (256 * QSTR)
#define QB_ELEMS (96 * QSTR)
#define QKVA_SMEM ((3 * QX_ELEMS + 2 * QB_ELEMS) * 2)   // 199,680 B

// 96x96 k-major B tile load, 768 threads, stride QSTR
#define CPA_BQ(BUF, SRC) \
  { \
    { int c_ = tid;       int r_ = c_ / 12, q_ = c_ % 12; \
      cp16(s2u(&(BUF)[r_ * QSTR + q_ * 8]), (SRC) + r_ * 96 + q_ * 8); } \
    { int c_ = tid + 768; if (c_ < 1152) { int r_ = c_ / 12, q_ = c_ % 12; \
      cp16(s2u(&(BUF)[r_ * QSTR + q_ * 8]), (SRC) + r_ * 96 + q_ * 8); } } \
  }

// K=96 MMA (256-row A tile, 24 warps: wr8 rows x wc3 cols), acc[2][4][4]
#define MMA_K96_Q(BB, ACC) \
  { \
    unsigned bb0 = s2u(&(BB)[lrow * QSTR + wc3 * 32 + lsel * 8]); \
    unsigned bb1 = bb0 + 16 * 2; \
    _Pragma("unroll") \
    for (int kc = 0; kc < 6; kc++) { \
      unsigned a[2][4], bt[2][4]; \
      ldsm4 (a[0],  aB0 + kc * 32); \
      ldsm4 (a[1],  aB1 + kc * 32); \
      ldsm4t(bt[0], bb0 + kc * (16 * QSTR * 2)); \
      ldsm4t(bt[1], bb1 + kc * (16 * QSTR * 2)); \
      _Pragma("unroll") \
      for (int mt = 0; mt < 2; mt++) \
        _Pragma("unroll") \
        for (int nt = 0; nt < 4; nt++) \
          mma_bf16(ACC[mt][nt], a[mt], bt[nt >> 1][(nt & 1) * 2], bt[nt >> 1][(nt & 1) * 2 + 1]); \
    } \
  }

// store acc tile to smem buffer DST (bf16, stride QSTR)
#define EPI_SMEM_Q(DST, ACC) \
  _Pragma("unroll") \
  for (int mt = 0; mt < 2; mt++) \
    _Pragma("unroll") \
    for (int nt = 0; nt < 4; nt++) { \
      int c0 = wc3 * 32 + nt * 8 + 2 * tig; \
      _Pragma("unroll") \
      for (int rr = 0; rr < 2; rr++) { \
        int rl = wr8 * 32 + mt * 16 + gid + rr * 8; \
        *reinterpret_cast<__nv_bfloat162*>(&(DST)[rl * QSTR + c0]) = \
            __float22bfloat162_rn(make_float2(ACC[mt][nt][2 * rr], ACC[mt][nt][2 * rr + 1])); \
      } \
    }

// ---- MEGA: LN1 + QKV + attention + proj + residual + noise1 -> g_x1 ----
__global__ void __launch_bounds__(768, 1) qkvap_kernel(const float* __restrict__ x,
                                                       const float* __restrict__ ln1g,
                                                       const float* __restrict__ ln1b,
                                                       const float* __restrict__ bp,
                                                       unsigned n1k0, unsigned n1k1) {
  extern __shared__ __align__(16) char smraw[];
  __nv_bfloat16* sm_x  = reinterpret_cast<__nv_bfloat16*>(smraw);   // LN(x) -> Q -> O
  __nv_bfloat16* sm_k  = sm_x + QX_ELEMS;
  __nv_bfloat16* sm_v  = sm_k + QX_ELEMS;
  __nv_bfloat16* sm_b0 = sm_v + QX_ELEMS;
  __nv_bfloat16* sm_b1 = sm_b0 + QB_ELEMS;
  int tid = threadIdx.x;
  int warp = tid >> 5, lane = tid & 31;
  int wr8 = warp / 3, wc3 = warp % 3;
  int gid = lane >> 2, tig = lane & 3;
  int lrow = lane & 15, lsel = lane >> 4;
  size_t tok0 = (size_t)blockIdx.x * 256;
  unsigned aB0 = s2u(&sm_x[(wr8 * 32 + lrow) * QSTR + lsel * 8]);
  unsigned aB1 = aB0 + 16 * QSTR * 2;

  CPA_BQ(sm_b0, g_wk)
  CP_COMMIT;
  // LN1 over 256 rows
  {
    float g0 = ln1g[lane], g1 = ln1g[lane + 32], g2 = ln1g[lane + 64];
    float b0 = ln1b[lane], b1 = ln1b[lane + 32], b2 = ln1b[lane + 64];
    for (int r = warp; r < 256; r += 24) {
      const float* xr = x + (tok0 + r) * 96;
      float v0 = xr[lane], v1 = xr[lane + 32], v2 = xr[lane + 64];
      float s = v0 + v1 + v2, sq = v0 * v0 + v1 * v1 + v2 * v2;
#pragma unroll
      for (int o = 16; o; o >>= 1) {
        s  += __shfl_xor_sync(0xffffffffu, s, o);
        sq += __shfl_xor_sync(0xffffffffu, sq, o);
      }
      float mu = s * (1.0f / 96.0f);
      float rs = rsqrtf(sq * (1.0f / 96.0f) - mu * mu + 1e-5f);
      sm_x[r * QSTR + lane]      = __float2bfloat16_rn((v0 - mu) * rs * g0 + b0);
      sm_x[r * QSTR + lane + 32] = __float2bfloat16_rn((v1 - mu) * rs * g1 + b1);
      sm_x[r * QSTR + lane + 64] = __float2bfloat16_rn((v2 - mu) * rs * g2 + b2);
    }
  }

  // K
  CP_WAIT(0); __syncthreads();
  CPA_BQ(sm_b1, g_wv) CP_COMMIT;
  {
    float acc[2][4][4] = {};
    MMA_K96_Q(sm_b0, acc)
    EPI_SMEM_Q(sm_k, acc)
  }
  // V
  CP_WAIT(0); __syncthreads();
  CPA_BQ(sm_b0, g_wq) CP_COMMIT;
  {
    float acc[2][4][4] = {};
    MMA_K96_Q(sm_b1, acc)
    EPI_SMEM_Q(sm_v, acc)
  }
  // Q (result to regs; Wp prefetch for proj)
  CP_WAIT(0); __syncthreads();
  CPA_BQ(sm_b1, g_wp) CP_COMMIT;
  float qacc[2][4][4] = {};
  MMA_K96_Q(sm_b0, qacc)
  __syncthreads();                 // all reads of LN'd sm_x complete
  EPI_SMEM_Q(sm_x, qacc)           // Q overwrites LN tile
  __syncthreads();                 // Q / K / V visible to all warps

  // ---- attention: warp -> head (warp%6), row-groups g and 7-g ----
  {
    int h = warp % 6;
    int coff = h * 16;
    int gbase = warp / 6;
    int krow_off = (lane & 7) + ((lane >> 4) << 3);
    int khalf = (lane >> 3) & 1;
#pragma unroll
    for (int task = 0; task < 2; task++) {
      int g = task ? (7 - gbase) : gbase;
      int r0 = g * 32;
      unsigned qa[2][4];
      ldsm4(qa[0], s2u(&sm_x[(r0 + lrow) * QSTR + coff + lsel * 8]));
      ldsm4(qa[1], s2u(&sm_x[(r0 + 16 + lrow) * QSTR + coff + lsel * 8]));
      float o[2][2][4] = {};
      float lsum[2][2] = {};
      int nkb = (r0 >> 6) + 1;
      for (int kbk = 0; kbk < nkb; kbk++) {
        bool diag = (kbk == nkb - 1);
#pragma unroll
        for (int h2 = 0; h2 < 2; h2++) {
          int cb2 = kbk * 64 + h2 * 32;
          unsigned kf[2][4];
          ldsm4(kf[0], s2u(&sm_k[(cb2 + krow_off) * QSTR + coff + khalf * 8]));
          ldsm4(kf[1], s2u(&sm_k[(cb2 + 16 + krow_off) * QSTR + coff + khalf * 8]));
          unsigned pa[2][2][4];
#pragma unroll
          for (int mt = 0; mt < 2; mt++) {
            int ra = r0 + mt * 16 + gid, rb = ra + 8;
            float s[4][4];
#pragma unroll
            for (int nt = 0; nt < 4; nt++) {
              s[nt][0] = s[nt][1] = s[nt][2] = s[nt][3] = 0.0f;
              mma_bf16(s[nt], qa[mt], kf[nt >> 1][(nt & 1) * 2], kf[nt >> 1][(nt & 1) * 2 + 1]);
            }
            if (diag) {
#pragma unroll
              for (int nt = 0; nt < 4; nt++) {
                int c0 = cb2 + nt * 8 + 2 * tig;
                float p0 = (c0     <= ra) ? __expf(s[nt][0] * 0.25f) : 0.0f;
                float p1 = (c0 + 1 <= ra) ? __expf(s[nt][1] * 0.25f) : 0.0f;
                float p2 = (c0     <= rb) ? __expf(s[nt][2] * 0.25f) : 0.0f;
                float p3 = (c0 + 1 <= rb) ? __expf(s[nt][3] * 0.25f) : 0.0f;
                lsum[mt][0] += p0 + p1;
                lsum[mt][1] += p2 + p3;
                pa[mt][nt >> 1][(nt & 1) * 2 + 0] = pack_bf2(p0, p1);
                pa[mt][nt >> 1][(nt & 1) * 2 + 1] = pack_bf2(p2, p3);
              }
            } else {
#pragma unroll
              for (int nt = 0; nt < 4; nt++) {
                float p0 = __expf(s[nt][0] * 0.25f);
                float p1 = __expf(s[nt][1] * 0.25f);
                float p2 = __expf(s[nt][2] * 0.25f);
                float p3 = __expf(s[nt][3] * 0.25f);
                lsum[mt][0] += p0 + p1;
                lsum[mt][1] += p2 + p3;
                pa[mt][nt >> 1][(nt & 1) * 2 + 0] = pack_bf2(p0, p1);
                pa[mt][nt >> 1][(nt & 1) * 2 + 1] = pack_bf2(p2, p3);
              }
            }
          }
#pragma unroll
          for (int kc = 0; kc < 2; kc++) {
            unsigned vt[4];
            ldsm4t(vt, s2u(&sm_v[(cb2 + kc * 16 + lrow) * QSTR + coff + lsel * 8]));
#pragma unroll
            for (int mt = 0; mt < 2; mt++) {
              mma_bf16(o[mt][0], pa[mt][kc], vt[0], vt[1]);
              mma_bf16(o[mt][1], pa[mt][kc], vt[2], vt[3]);
            }
          }
        }
      }
#pragma unroll
      for (int mt = 0; mt < 2; mt++)
#pragma unroll
        for (int rr = 0; rr < 2; rr++) {
          float v = lsum[mt][rr];
          v += __shfl_xor_sync(0xffffffffu, v, 1);
          v += __shfl_xor_sync(0xffffffffu, v, 2);
          lsum[mt][rr] = 1.0f / v;
        }
      // O overwrites Q region (g,h) of sm_x — warp-private region
#pragma unroll
      for (int mt = 0; mt < 2; mt++) {
        int ra = r0 + mt * 16 + gid, rb = ra + 8;
#pragma unroll
        for (int nt = 0; nt < 2; nt++) {
          int c = coff + nt * 8 + 2 * tig;
          *reinterpret_cast<__nv_bfloat162*>(&sm_x[ra * QSTR + c]) =
              __float22bfloat162_rn(make_float2(o[mt][nt][0] * lsum[mt][0], o[mt][nt][1] * lsum[mt][0]));
          *reinterpret_cast<__nv_bfloat162*>(&sm_x[rb * QSTR + c]) =
              __float22bfloat162_rn(make_float2(o[mt][nt][2] * lsum[mt][1], o[mt][nt][3] * lsum[mt][1]));
        }
      }
    }
  }
  __syncthreads();                 // O tile complete

  // ---- proj: O @ Wp + x + bp + noise1 -> g_x1 ----
  CP_WAIT(0);                      // Wp (arrived during attention)
  float acc[2][4][4] = {};
  MMA_K96_Q(sm_b1, acc)
#pragma unroll
  for (int mt = 0; mt < 2; mt++)
#pragma unroll
    for (int nt = 0; nt < 4; nt++) {
      int c0 = wc3 * 32 + nt * 8 + 2 * tig;
      float bp0 = bp[c0], bp1 = bp[c0 + 1];
#pragma unroll
      for (int rr = 0; rr < 2; rr++) {
        int rl = wr8 * 32 + mt * 16 + gid + rr * 8;
        unsigned i0 = (unsigned)((tok0 + rl) * 96 + c0);
        float2 xv = *reinterpret_cast<const float2*>(&x[i0]);
        *reinterpret_cast<float2*>(&g_x1[i0]) =
            make_float2(xv.x + acc[mt][nt][2 * rr]     + bp0 + jax_noise(n1k0, n1k1, i0),
                        xv.y + acc[mt][nt][2 * rr + 1] + bp1 + jax_noise(n1k0, n1k1, i0 + 1));
      }
    }
}

// ============ ff kernel geometry (unchanged from R12) ============
#define SASTRIDE 136
#define FSTRIDE  392
#define A_ELEMS (128 * SASTRIDE)
#define B_ELEMS (96 * SASTRIDE)
#define F_ELEMS (128 * FSTRIDE)
#define FF_SMEM_BYTES ((A_ELEMS + F_ELEMS + 2 * B_ELEMS) * 2)

#define CPA_B_768(BUF, SRC, LD, OFF) \
  _Pragma("unroll") \
  for (int i = 0; i < 2; i++) { \
    int c = tid + i * 768; \
    if (c < 1152) { \
      int r = c / 12, q = c % 12; \
      cp16(s2u(&(BUF)[r * SASTRIDE + q * 8]), (SRC) + r * (LD) + (OFF) + q * 8); \
    } \
  }

#define MMA_K96_768(BB, AB0, AB1, KOFF, ACC) \
  { \
    unsigned bb0 = s2u(&(BB)[lrow * SASTRIDE + wc6 * 16 + lsel * 8]); \
    _Pragma("unroll") \
    for (int kc = 0; kc < 6; kc++) { \
      unsigned a[2][4], bt[4]; \
      ldsm4 (a[0],  (AB0) + (KOFF) + kc * 32); \
      ldsm4 (a[1],  (AB1) + (KOFF) + kc * 32); \
      ldsm4t(bt,    bb0 + kc * (16 * SASTRIDE * 2)); \
      _Pragma("unroll") \
      for (int mt = 0; mt < 2; mt++) \
        _Pragma("unroll") \
        for (int nt = 0; nt < 2; nt++) \
          mma_bf16(ACC[mt][nt], a[mt], bt[nt * 2], bt[nt * 2 + 1]); \
    } \
  }

// ---- fused LN2 + FF1 + FF2 + residual + noise2 -> out (768 threads / 24 warps) ----
__global__ void __launch_bounds__(768, 1) ff_kernel(const float* __restrict__ b1,
                                                    const float* __restrict__ b2,
                                                    const float* __restrict__ ln2g,
                                                    const float* __restrict__ ln2b,
                                                    float* __restrict__ out,
                                                    unsigned nk0, unsigned nk1v) {
  extern __shared__ __align__(16) char smraw[];
  __nv_bfloat16* sm_a  = reinterpret_cast<__nv_bfloat16*>(smraw);
  __nv_bfloat16* sm_f  = sm_a + A_ELEMS;
  __nv_bfloat16* sm_b0 = sm_f + F_ELEMS;
  __nv_bfloat16* sm_b1 = sm_b0 + B_ELEMS;
  int tid = threadIdx.x;
  int warp = tid >> 5, lane = tid & 31;
  int wr6 = warp / 6, wc6 = warp % 6;
  int gid = lane >> 2, tig = lane & 3;
  int lrow = lane & 15, lsel = lane >> 4;
  int row0 = blockIdx.x * 128;
  unsigned aB0 = s2u(&sm_a[(wr6 * 32 + lrow) * SASTRIDE + lsel * 8]);
  unsigned aB1 = aB0 + 16 * SASTRIDE * 2;
  unsigned fB0 = s2u(&sm_f[(wr6 * 32 + lrow) * FSTRIDE + lsel * 8]);
  unsigned fB1 = fB0 + 16 * FSTRIDE * 2;

  CPA_B_768(sm_b0, g_w1c, 384, 0)
  CP_COMMIT;
  {
    float g0 = ln2g[lane], g1 = ln2g[lane + 32], g2 = ln2g[lane + 64];
    float b0 = ln2b[lane], b1v = ln2b[lane + 32], b2v = ln2b[lane + 64];
    for (int r = warp; r < 128; r += 24) {
      const float* xr = g_x1 + (size_t)(row0 + r) * 96;
      float s0 = xr[lane], s1 = xr[lane + 32], s2 = xr[lane + 64];
      float s = s0 + s1 + s2, sq = s0 * s0 + s1 * s1 + s2 * s2;
#pragma unroll
      for (int o = 16; o; o >>= 1) {
        s  += __shfl_xor_sync(0xffffffffu, s, o);
        sq += __shfl_xor_sync(0xffffffffu, sq, o);
      }
      float mu = s * (1.0f / 96.0f);
      float rs = rsqrtf(sq * (1.0f / 96.0f) - mu * mu + 1e-5f);
      sm_a[r * SASTRIDE + lane]      = __float2bfloat16_rn((s0 - mu) * rs * g0 + b0);
      sm_a[r * SASTRIDE + lane + 32] = __float2bfloat16_rn((s1 - mu) * rs * g1 + b1v);
      sm_a[r * SASTRIDE + lane + 64] = __float2bfloat16_rn((s2 - mu) * rs * g2 + b2v);
    }
  }

  float acc2[2][2][4] = {};
  for (int t = 0; t < 8; t++) {
    CP_WAIT(0);
    __syncthreads();
    if (t < 7) {
      int tn = t + 1;
      const __nv_bfloat16* src = (tn < 4) ? g_w1c : (g_w2c + (tn - 4) * 9216);
      int ld  = (tn < 4) ? 384 : 96;
      int off = (tn < 4) ? tn * 96 : 0;
      if (tn & 1) { CPA_B_768(sm_b1, src, ld, off) } else { CPA_B_768(sm_b0, src, ld, off) }
      CP_COMMIT;
    }
    if (t < 4) {
      float acc[2][2][4] = {};
      if (t & 1) { MMA_K96_768(sm_b1, aB0, aB1, 0, acc) }
      else       { MMA_K96_768(sm_b0, aB0, aB1, 0, acc) }
      int co = t * 96;
#pragma unroll
      for (int mt = 0; mt < 2; mt++)
#pragma unroll
        for (int nt = 0; nt < 2; nt++) {
          int c0 = wc6 * 16 + nt * 8 + 2 * tig;
          float bb0 = b1[co + c0], bb1 = b1[co + c0 + 1];
#pragma unroll
          for (int rr = 0; rr < 2; rr++) {
            int rl = wr6 * 32 + mt * 16 + gid + rr * 8;
            *reinterpret_cast<__nv_bfloat162*>(&sm_f[rl * FSTRIDE + co + c0]) =
                __float22bfloat162_rn(make_float2(fmaxf(acc[mt][nt][2 * rr] + bb0, 0.0f),
                                                  fmaxf(acc[mt][nt][2 * rr + 1] + bb1, 0.0f)));
          }
        }
    } else {
      int goff = (t - 4) * 192;
      if (t & 1) { MMA_K96_768(sm_b1, fB0, fB1, goff, acc2) }
      else       { MMA_K96_768(sm_b0, fB0, fB1, goff, acc2) }
    }
  }
#pragma unroll
  for (int mt = 0; mt < 2; mt++)
#pragma unroll
    for (int nt = 0; nt < 2; nt++) {
      int r0 = row0 + wr6 * 32 + mt * 16 + gid;
      int c0 = wc6 * 16 + nt * 8 + 2 * tig;
      float bb0 = b2[c0], bb1 = b2[c0 + 1];
#pragma unroll
      for (int rr = 0; rr < 2; rr++) {
        int i0 = (r0 + rr * 8) * 96 + c0;
        float2 xv = *reinterpret_cast<const float2*>(&g_x1[i0]);
        *reinterpret_cast<float2*>(&out[i0]) =
            make_float2(xv.x + acc2[mt][nt][2 * rr]     + bb0 + jax_noise(nk0, nk1v, (unsigned)i0),
                        xv.y + acc2[mt][nt][2 * rr + 1] + bb1 + jax_noise(nk0, nk1v, (unsigned)(i0 + 1)));
      }
    }
}

extern "C" void kernel_launch(void* const* d_in, const int* in_sizes, int n_in,
                              void* d_out, int out_size) {
  (void)in_sizes; (void)n_in; (void)out_size;
  const float* x    = (const float*)d_in[0];
  const float* Wq   = (const float*)d_in[1];
  const float* Wk   = (const float*)d_in[2];
  const float* Wv   = (const float*)d_in[3];
  const float* Wp   = (const float*)d_in[4];
  const float* bp   = (const float*)d_in[5];
  const float* ln1g = (const float*)d_in[6];
  const float* ln1b = (const float*)d_in[7];
  const float* ln2g = (const float*)d_in[8];
  const float* ln2b = (const float*)d_in[9];
  const float* W1   = (const float*)d_in[10];
  const float* b1   = (const float*)d_in[11];
  const float* W2   = (const float*)d_in[12];
  const float* b2   = (const float*)d_in[13];
  float* out = (float*)d_out;

  unsigned nk1_0, nk1_1, nk2_0, nk2_1;
  tf2x32(0u, 42u, 0u, 0u, nk1_0, nk1_1);
  tf2x32(0u, 42u, 0u, 1u, nk2_0, nk2_1);

  cudaFuncSetAttribute(qkvap_kernel, cudaFuncAttributeMaxDynamicSharedMemorySize, QKVA_SMEM);
  cudaFuncSetAttribute(ff_kernel,    cudaFuncAttributeMaxDynamicSharedMemorySize, FF_SMEM_BYTES);

  prep_kernel <<<324, 256>>>(Wq, Wk, Wv, Wp, W1, W2);
  qkvap_kernel<<<256, 768, QKVA_SMEM>>>(x, ln1g, ln1b, bp, nk1_0, nk1_1);
  ff_kernel   <<<512, 768, FF_SMEM_BYTES>>>(b1, b2, ln2g, ln2b, out, nk2_0, nk2_1);
}

// round 15
// speedup vs baseline: 1.2417x; 1.1181x over previous
#include <cuda_runtime.h>
#include <cuda_bf16.h>
#include <cstdint>

// Problem dims: B=256, T=256, D=96, H=6, E=16, DFF=384

// pre-converted bf16 weights (k-major [k][n] layouts)
__device__ __nv_bfloat16 g_wq[96 * 96];
__device__ __nv_bfloat16 g_wk[96 * 96];
__device__ __nv_bfloat16 g_wv[96 * 96];
__device__ __nv_bfloat16 g_wp[96 * 96];
__device__ __nv_bfloat16 g_w1c[96 * 384];
__device__ __nv_bfloat16 g_w2c[384 * 96];

// ---------------- bf16 mma + ldmatrix + cp.async helpers ----------------
__device__ __forceinline__ void ldsm4(unsigned (&r)[4], unsigned addr) {
  asm volatile("ldmatrix.sync.aligned.m8n8.x4.shared.b16 {%0,%1,%2,%3}, [%4];"
               : "=r"(r[0]), "=r"(r[1]), "=r"(r[2]), "=r"(r[3]) : "r"(addr));
}
__device__ __forceinline__ void ldsm4t(unsigned (&r)[4], unsigned addr) {
  asm volatile("ldmatrix.sync.aligned.m8n8.x4.trans.shared.b16 {%0,%1,%2,%3}, [%4];"
               : "=r"(r[0]), "=r"(r[1]), "=r"(r[2]), "=r"(r[3]) : "r"(addr));
}
__device__ __forceinline__ void mma_bf16(float (&d)[4], const unsigned (&a)[4], unsigned b0, unsigned b1) {
  asm volatile("mma.sync.aligned.m16n8k16.row.col.f32.bf16.bf16.f32 "
               "{%0,%1,%2,%3}, {%4,%5,%6,%7}, {%8,%9}, {%0,%1,%2,%3};"
               : "+f"(d[0]), "+f"(d[1]), "+f"(d[2]), "+f"(d[3])
               : "r"(a[0]), "r"(a[1]), "r"(a[2]), "r"(a[3]), "r"(b0), "r"(b1));
}
__device__ __forceinline__ unsigned s2u(const void* p) {
  return (unsigned)__cvta_generic_to_shared(p);
}
__device__ __forceinline__ void cp16(unsigned dst, const void* src) {
  asm volatile("cp.async.cg.shared.global [%0], [%1], 16;" :: "r"(dst), "l"(src));
}
#define CP_COMMIT asm volatile("cp.async.commit_group;")
#define CP_WAIT(N) asm volatile("cp.async.wait_group %0;" :: "n"(N))
__device__ __forceinline__ unsigned pack_bf2(float lo, float hi) {
  __nv_bfloat162 h = __float22bfloat162_rn(make_float2(lo, hi));
  return *reinterpret_cast<unsigned*>(&h);
}

// ---------------- JAX threefry-2x32 (20 rounds) ----------------
__host__ __device__ __forceinline__ void tf2x32(unsigned k0, unsigned k1,
                                                unsigned x0, unsigned x1,
                                                unsigned &o0, unsigned &o1) {
  unsigned k2 = k0 ^ k1 ^ 0x1BD11BDAu;
  unsigned v0 = x0 + k0, v1 = x1 + k1;
#define TFR(r) { v0 += v1; v1 = (v1 << (r)) | (v1 >> (32 - (r))); v1 ^= v0; }
  TFR(13) TFR(15) TFR(26) TFR(6)   v0 += k1; v1 += k2 + 1u;
  TFR(17) TFR(29) TFR(16) TFR(24)  v0 += k2; v1 += k0 + 2u;
  TFR(13) TFR(15) TFR(26) TFR(6)   v0 += k0; v1 += k1 + 3u;
  TFR(17) TFR(29) TFR(16) TFR(24)  v0 += k1; v1 += k2 + 4u;
  TFR(13) TFR(15) TFR(26) TFR(6)   v0 += k2; v1 += k0 + 5u;
#undef TFR
  o0 = v0; o1 = v1;
}

__device__ __forceinline__ float jax_noise(unsigned k0, unsigned k1, unsigned idx) {
  unsigned o0, o1;
  tf2x32(k0, k1, 0u, idx, o0, o1);
  unsigned bits = o0 ^ o1;
  float u = __uint_as_float((bits >> 9) | 0x3f800000u) - 1.0f;
  const float lo = -0.99999994f;
  float val = u * 1.99999994f + lo;
  val = fmaxf(lo, val);
  return 0.1f * (1.4142135381698608f * erfinvf(val));
}

// ---------------- weight prep: fp32 -> bf16, gather into [k][n] ----------------
__global__ void __launch_bounds__(256) prep_kernel(const float* __restrict__ Wq,
                                                   const float* __restrict__ Wk,
                                                   const float* __restrict__ Wv,
                                                   const float* __restrict__ Wp,
                                                   const float* __restrict__ W1,
                                                   const float* __restrict__ W2) {
  int i = blockIdx.x * 256 + threadIdx.x;
  if (i < 9216) {
    int r = i / 96, c = i % 96;
    int h = c >> 4, e = c & 15;
    int s = h * 1536 + r * 16 + e;
    g_wq[i] = __float2bfloat16_rn(Wq[s]);
    g_wk[i] = __float2bfloat16_rn(Wk[s]);
    g_wv[i] = __float2bfloat16_rn(Wv[s]);
    g_wp[i] = __float2bfloat16_rn(Wp[i]);
  } else if (i < 9216 + 36864) {
    int j = i - 9216;
    g_w1c[j] = __float2bfloat16_rn(W1[j]);
  } else if (i < 9216 + 2 * 36864) {
    int j = i - 9216 - 36864;
    g_w2c[j] = __float2bfloat16_rn(W2[j]);
  }
}

// ============ mega-kernel smem geometry (bf16 elems) ============
// all ldsm strides are multiples of 8 elems (16 B) and ≡ 20 mod 32 words -> conflict-free
#define QSTR  104
#define X1STR 100                 // fp32 rows (400 B, only float2 access; 100 ≡ 4 mod 32 words)
#define OFF_X   0                 // sm_x: 256x104 (LN1 -> Q -> O -> LN2)
#define OFF_K   26624             // sm_k: 256x104; x1 (fp32) region starts here later
#define OFF_V   53248             // sm_v: 256x104 (ends 79872)
#define OFF_FG  77824             // Fg: 256x104 (starts at x1 end; overlaps dead V tail)
#define OFF_B0  104448            // B0: 96x104
#define TOT_ELEMS 114432
#define MEGA_SMEM (TOT_ELEMS * 2) // 228,864 B

// 96-row k-major B tile load, 768 threads, dst stride QSTR
#define CPA_BW(BUF, SRC, LD, OFF) \
  { \
    { int c_ = tid;       int r_ = c_ / 12, q_ = c_ % 12; \
      cp16(s2u(&(BUF)[r_ * QSTR + q_ * 8]), (SRC) + r_ * (LD) + (OFF) + q_ * 8); } \
    { int c_ = tid + 768; if (c_ < 1152) { int r_ = c_ / 12, q_ = c_ % 12; \
      cp16(s2u(&(BUF)[r_ * QSTR + q_ * 8]), (SRC) + r_ * (LD) + (OFF) + q_ * 8); } } \
  }

// K=96 MMA: A frags at (A0,A1), B tile BB (stride QSTR), acc[2][4][4]
#define MMA_K96(BB, A0, A1, ACC) \
  { \
    unsigned bb0 = s2u(&(BB)[lrow * QSTR + wc3 * 32 + lsel * 8]); \
    unsigned bb1 = bb0 + 16 * 2; \
    _Pragma("unroll") \
    for (int kc = 0; kc < 6; kc++) { \
      unsigned a[2][4], bt[2][4]; \
      ldsm4 (a[0],  (A0) + kc * 32); \
      ldsm4 (a[1],  (A1) + kc * 32); \
      ldsm4t(bt[0], bb0 + kc * (16 * QSTR * 2)); \
      ldsm4t(bt[1], bb1 + kc * (16 * QSTR * 2)); \
      _Pragma("unroll") \
      for (int mt = 0; mt < 2; mt++) \
        _Pragma("unroll") \
        for (int nt = 0; nt < 4; nt++) \
          mma_bf16(ACC[mt][nt], a[mt], bt[nt >> 1][(nt & 1) * 2], bt[nt >> 1][(nt & 1) * 2 + 1]); \
    } \
  }

// store acc tile to smem DST (bf16, stride QSTR)
#define EPI_SMEM(DST, ACC) \
  _Pragma("unroll") \
  for (int mt = 0; mt < 2; mt++) \
    _Pragma("unroll") \
    for (int nt = 0; nt < 4; nt++) { \
      int c0 = wc3 * 32 + nt * 8 + 2 * tig; \
      _Pragma("unroll") \
      for (int rr = 0; rr < 2; rr++) { \
        int rl = wr8 * 32 + mt * 16 + gid + rr * 8; \
        *reinterpret_cast<__nv_bfloat162*>(&(DST)[rl * QSTR + c0]) = \
            __float22bfloat162_rn(make_float2(ACC[mt][nt][2 * rr], ACC[mt][nt][2 * rr + 1])); \
      } \
    }

// ---- MEGA: full decoder block per batch ----
__global__ void __launch_bounds__(768, 1) block_kernel(const float* __restrict__ x,
                                                       const float* __restrict__ ln1g,
                                                       const float* __restrict__ ln1b,
                                                       const float* __restrict__ bp,
                                                       const float* __restrict__ b1v_,
                                                       const float* __restrict__ b2v_,
                                                       const float* __restrict__ ln2g,
                                                       const float* __restrict__ ln2b,
                                                       float* __restrict__ out,
                                                       unsigned n1k0, unsigned n1k1,
                                                       unsigned n2k0, unsigned n2k1) {
  extern __shared__ __align__(16) char smraw[];
  __nv_bfloat16* smb = reinterpret_cast<__nv_bfloat16*>(smraw);
  __nv_bfloat16* sm_x  = smb + OFF_X;
  __nv_bfloat16* sm_k  = smb + OFF_K;
  __nv_bfloat16* sm_v  = smb + OFF_V;
  __nv_bfloat16* sm_fg = smb + OFF_FG;
  __nv_bfloat16* sm_b0 = smb + OFF_B0;
  float* x1f = reinterpret_cast<float*>(smb + OFF_K);   // 256 x X1STR fp32 (post-attention)

  int tid = threadIdx.x;
  int warp = tid >> 5, lane = tid & 31;
  int wr8 = warp / 3, wc3 = warp % 3;
  int gid = lane >> 2, tig = lane & 3;
  int lrow = lane & 15, lsel = lane >> 4;
  size_t tok0 = (size_t)blockIdx.x * 256;
  unsigned aX0 = s2u(&sm_x[(wr8 * 32 + lrow) * QSTR + lsel * 8]);
  unsigned aX1 = aX0 + 16 * QSTR * 2;
  unsigned aF0 = s2u(&sm_fg[(wr8 * 32 + lrow) * QSTR + lsel * 8]);
  unsigned aF1 = aF0 + 16 * QSTR * 2;

  CPA_BW(sm_b0, g_wk, 96, 0)
  CP_COMMIT;
  // LN1 over 256 rows
  {
    float g0 = ln1g[lane], g1 = ln1g[lane + 32], g2 = ln1g[lane + 64];
    float b0 = ln1b[lane], b1 = ln1b[lane + 32], b2 = ln1b[lane + 64];
    for (int r = warp; r < 256; r += 24) {
      const float* xr = x + (tok0 + r) * 96;
      float v0 = xr[lane], v1 = xr[lane + 32], v2 = xr[lane + 64];
      float s = v0 + v1 + v2, sq = v0 * v0 + v1 * v1 + v2 * v2;
#pragma unroll
      for (int o = 16; o; o >>= 1) {
        s  += __shfl_xor_sync(0xffffffffu, s, o);
        sq += __shfl_xor_sync(0xffffffffu, sq, o);
      }
      float mu = s * (1.0f / 96.0f);
      float rs = rsqrtf(sq * (1.0f / 96.0f) - mu * mu + 1e-5f);
      sm_x[r * QSTR + lane]      = __float2bfloat16_rn((v0 - mu) * rs * g0 + b0);
      sm_x[r * QSTR + lane + 32] = __float2bfloat16_rn((v1 - mu) * rs * g1 + b1);
      sm_x[r * QSTR + lane + 64] = __float2bfloat16_rn((v2 - mu) * rs * g2 + b2);
    }
  }

  // ---- K ----
  CP_WAIT(0); __syncthreads();                // wk ready, LN1 visible
  {
    float acc[2][4][4] = {};
    MMA_K96(sm_b0, aX0, aX1, acc)
    __syncthreads();                          // all warps done reading b0
    CPA_BW(sm_b0, g_wv, 96, 0) CP_COMMIT;
    EPI_SMEM(sm_k, acc)
  }
  // ---- V ----
  CP_WAIT(0); __syncthreads();                // wv ready; sm_k visible
  {
    float acc[2][4][4] = {};
    MMA_K96(sm_b0, aX0, aX1, acc)
    __syncthreads();
    CPA_BW(sm_b0, g_wq, 96, 0) CP_COMMIT;
    EPI_SMEM(sm_v, acc)
  }
  // ---- Q ----
  CP_WAIT(0); __syncthreads();                // wq ready; sm_v visible
  float qacc[2][4][4] = {};
  MMA_K96(sm_b0, aX0, aX1, qacc)
  __syncthreads();                            // b0 reads + all sm_x (LN) reads done
  CPA_BW(sm_b0, g_wp, 96, 0) CP_COMMIT;       // Wp streams in during attention
  EPI_SMEM(sm_x, qacc)                        // Q overwrites LN tile
  __syncthreads();                            // Q/K/V visible

  // ---- attention: warp -> head (warp%6), row-groups gbase and 7-gbase ----
  {
    int h = warp % 6;
    int coff = h * 16;
    int gbase = warp / 6;
    int krow_off = (lane & 7) + ((lane >> 4) << 3);
    int khalf = (lane >> 3) & 1;
#pragma unroll
    for (int task = 0; task < 2; task++) {
      int g = task ? (7 - gbase) : gbase;
      int r0 = g * 32;
      unsigned qa[2][4];
      ldsm4(qa[0], s2u(&sm_x[(r0 + lrow) * QSTR + coff + lsel * 8]));
      ldsm4(qa[1], s2u(&sm_x[(r0 + 16 + lrow) * QSTR + coff + lsel * 8]));
      float o[2][2][4] = {};
      float lsum[2][2] = {};
      int nkb = (r0 >> 6) + 1;
      for (int kbk = 0; kbk < nkb; kbk++) {
        bool diag = (kbk == nkb - 1);
#pragma unroll
        for (int h2 = 0; h2 < 2; h2++) {
          int cb2 = kbk * 64 + h2 * 32;
          unsigned kf[2][4];
          ldsm4(kf[0], s2u(&sm_k[(cb2 + krow_off) * QSTR + coff + khalf * 8]));
          ldsm4(kf[1], s2u(&sm_k[(cb2 + 16 + krow_off) * QSTR + coff + khalf * 8]));
          unsigned pa[2][2][4];
#pragma unroll
          for (int mt = 0; mt < 2; mt++) {
            int ra = r0 + mt * 16 + gid, rb = ra + 8;
            float s[4][4];
#pragma unroll
            for (int nt = 0; nt < 4; nt++) {
              s[nt][0] = s[nt][1] = s[nt][2] = s[nt][3] = 0.0f;
              mma_bf16(s[nt], qa[mt], kf[nt >> 1][(nt & 1) * 2], kf[nt >> 1][(nt & 1) * 2 + 1]);
            }
            if (diag) {
#pragma unroll
              for (int nt = 0; nt < 4; nt++) {
                int c0 = cb2 + nt * 8 + 2 * tig;
                float p0 = (c0     <= ra) ? __expf(s[nt][0] * 0.25f) : 0.0f;
                float p1 = (c0 + 1 <= ra) ? __expf(s[nt][1] * 0.25f) : 0.0f;
                float p2 = (c0     <= rb) ? __expf(s[nt][2] * 0.25f) : 0.0f;
                float p3 = (c0 + 1 <= rb) ? __expf(s[nt][3] * 0.25f) : 0.0f;
                lsum[mt][0] += p0 + p1;
                lsum[mt][1] += p2 + p3;
                pa[mt][nt >> 1][(nt & 1) * 2 + 0] = pack_bf2(p0, p1);
                pa[mt][nt >> 1][(nt & 1) * 2 + 1] = pack_bf2(p2, p3);
              }
            } else {
#pragma unroll
              for (int nt = 0; nt < 4; nt++) {
                float p0 = __expf(s[nt][0] * 0.25f);
                float p1 = __expf(s[nt][1] * 0.25f);
                float p2 = __expf(s[nt][2] * 0.25f);
                float p3 = __expf(s[nt][3] * 0.25f);
                lsum[mt][0] += p0 + p1;
                lsum[mt][1] += p2 + p3;
                pa[mt][nt >> 1][(nt & 1) * 2 + 0] = pack_bf2(p0, p1);
                pa[mt][nt >> 1][(nt & 1) * 2 + 1] = pack_bf2(p2, p3);
              }
            }
          }
#pragma unroll
          for (int kc = 0; kc < 2; kc++) {
            unsigned vt[4];
            ldsm4t(vt, s2u(&sm_v[(cb2 + kc * 16 + lrow) * QSTR + coff + lsel * 8]));
#pragma unroll
            for (int mt = 0; mt < 2; mt++) {
              mma_bf16(o[mt][0], pa[mt][kc], vt[0], vt[1]);
              mma_bf16(o[mt][1], pa[mt][kc], vt[2], vt[3]);
            }
          }
        }
      }
#pragma unroll
      for (int mt = 0; mt < 2; mt++)
#pragma unroll
        for (int rr = 0; rr < 2; rr++) {
          float v = lsum[mt][rr];
          v += __shfl_xor_sync(0xffffffffu, v, 1);
          v += __shfl_xor_sync(0xffffffffu, v, 2);
          lsum[mt][rr] = 1.0f / v;
        }
#pragma unroll
      for (int mt = 0; mt < 2; mt++) {
        int ra = r0 + mt * 16 + gid, rb = ra + 8;
#pragma unroll
        for (int nt = 0; nt < 2; nt++) {
          int c = coff + nt * 8 + 2 * tig;
          *reinterpret_cast<__nv_bfloat162*>(&sm_x[ra * QSTR + c]) =
              __float22bfloat162_rn(make_float2(o[mt][nt][0] * lsum[mt][0], o[mt][nt][1] * lsum[mt][0]));
          *reinterpret_cast<__nv_bfloat162*>(&sm_x[rb * QSTR + c]) =
              __float22bfloat162_rn(make_float2(o[mt][nt][2] * lsum[mt][1], o[mt][nt][3] * lsum[mt][1]));
        }
      }
    }
  }
  __syncthreads();                 // O complete; K/V dead from here

  // ---- proj: O @ Wp; x1 = x + proj + bp + noise1 -> smem fp32 ----
  CP_WAIT(0);                      // Wp in b0
  {
    float acc[2][4][4] = {};
    MMA_K96(sm_b0, aX0, aX1, acc)
    __syncthreads();               // all b0 reads done
    CPA_BW(sm_b0, g_w1c, 384, 0)   // prefetch W1[0]
    CP_COMMIT;
#pragma unroll
    for (int mt = 0; mt < 2; mt++)
#pragma unroll
      for (int nt = 0; nt < 4; nt++) {
        int c0 = wc3 * 32 + nt * 8 + 2 * tig;
        float bp0 = bp[c0], bp1 = bp[c0 + 1];
#pragma unroll
        for (int rr = 0; rr < 2; rr++) {
          int rl = wr8 * 32 + mt * 16 + gid + rr * 8;
          unsigned i0 = (unsigned)((tok0 + rl) * 96 + c0);
          float2 xv = *reinterpret_cast<const float2*>(&x[i0]);
          *reinterpret_cast<float2*>(&x1f[rl * X1STR + c0]) =
              make_float2(xv.x + acc[mt][nt][2 * rr]     + bp0 + jax_noise(n1k0, n1k1, i0),
                          xv.y + acc[mt][nt][2 * rr + 1] + bp1 + jax_noise(n1k0, n1k1, i0 + 1));
        }
      }
  }
  __syncthreads();                 // x1 complete; sm_x (O) reads done

  // ---- LN2: x1(smem) -> sm_x (bf16) ----
  {
    float g0 = ln2g[lane], g1 = ln2g[lane + 32], g2 = ln2g[lane + 64];
    float b0 = ln2b[lane], b1 = ln2b[lane + 32], b2 = ln2b[lane + 64];
    for (int r = warp; r < 256; r += 24) {
      const float* xr = &x1f[r * X1STR];
      float v0 = xr[lane], v1 = xr[lane + 32], v2 = xr[lane + 64];
      float s = v0 + v1 + v2, sq = v0 * v0 + v1 * v1 + v2 * v2;
#pragma unroll
      for (int o = 16; o; o >>= 1) {
        s  += __shfl_xor_sync(0xffffffffu, s, o);
        sq += __shfl_xor_sync(0xffffffffu, sq, o);
      }
      float mu = s * (1.0f / 96.0f);
      float rs = rsqrtf(sq * (1.0f / 96.0f) - mu * mu + 1e-5f);
      sm_x[r * QSTR + lane]      = __float2bfloat16_rn((v0 - mu) * rs * g0 + b0);
      sm_x[r * QSTR + lane + 32] = __float2bfloat16_rn((v1 - mu) * rs * g1 + b1);
      sm_x[r * QSTR + lane + 64] = __float2bfloat16_rn((v2 - mu) * rs * g2 + b2);
    }
  }

  // ---- FF: 4 groups; FF1 -> Fg; FF2 accumulates into x1 smem ----
  for (int g = 0; g < 4; g++) {
    CP_WAIT(0);                    // W1[g] in b0
    __syncthreads();               // LN2 (g=0) / Fg reads of prev iter visible-safe
    float facc[2][4][4] = {};
    MMA_K96(sm_b0, aX0, aX1, facc) // FF1 group g
    __syncthreads();               // b0 reads done
    CPA_BW(sm_b0, g_w2c + g * 9216, 96, 0)
    CP_COMMIT;
    {
      int co = g * 96;
#pragma unroll
      for (int mt = 0; mt < 2; mt++)
#pragma unroll
        for (int nt = 0; nt < 4; nt++) {
          int c0 = wc3 * 32 + nt * 8 + 2 * tig;
          float bb0 = b1v_[co + c0], bb1 = b1v_[co + c0 + 1];
#pragma unroll
          for (int rr = 0; rr < 2; rr++) {
            int rl = wr8 * 32 + mt * 16 + gid + rr * 8;
            *reinterpret_cast<__nv_bfloat162*>(&sm_fg[rl * QSTR + c0]) =
                __float22bfloat162_rn(make_float2(fmaxf(facc[mt][nt][2 * rr] + bb0, 0.0f),
                                                  fmaxf(facc[mt][nt][2 * rr + 1] + bb1, 0.0f)));
          }
        }
    }
    CP_WAIT(0);
    __syncthreads();               // Fg visible + W2[g] arrived
    float tacc[2][4][4] = {};
    MMA_K96(sm_b0, aF0, aF1, tacc) // FF2 chunk g
#pragma unroll
    for (int mt = 0; mt < 2; mt++)
#pragma unroll
      for (int nt = 0; nt < 4; nt++) {
        int c0 = wc3 * 32 + nt * 8 + 2 * tig;
#pragma unroll
        for (int rr = 0; rr < 2; rr++) {
          int rl = wr8 * 32 + mt * 16 + gid + rr * 8;
          float2 v = *reinterpret_cast<float2*>(&x1f[rl * X1STR + c0]);
          v.x += tacc[mt][nt][2 * rr];
          v.y += tacc[mt][nt][2 * rr + 1];
          *reinterpret_cast<float2*>(&x1f[rl * X1STR + c0]) = v;
        }
      }
    __syncthreads();               // b0 + Fg reads done before next overwrite
    if (g < 3) { CPA_BW(sm_b0, g_w1c, 384, (g + 1) * 96) CP_COMMIT; }
  }

  // ---- final epilogue: out = x1(+ff2) + b2 + noise2 (thread-owned elems) ----
#pragma unroll
  for (int mt = 0; mt < 2; mt++)
#pragma unroll
    for (int nt = 0; nt < 4; nt++) {
      int c0 = wc3 * 32 + nt * 8 + 2 * tig;
      float bb0 = b2v_[c0], bb1 = b2v_[c0 + 1];
#pragma unroll
      for (int rr = 0; rr < 2; rr++) {
        int rl = wr8 * 32 + mt * 16 + gid + rr * 8;
        unsigned i0 = (unsigned)((tok0 + rl) * 96 + c0);
        float2 v = *reinterpret_cast<float2*>(&x1f[rl * X1STR + c0]);
        *reinterpret_cast<float2*>(&out[i0]) =
            make_float2(v.x + bb0 + jax_noise(n2k0, n2k1, i0),
                        v.y + bb1 + jax_noise(n2k0, n2k1, i0 + 1));
      }
    }
}

extern "C" void kernel_launch(void* const* d_in, const int* in_sizes, int n_in,
                              void* d_out, int out_size) {
  (void)in_sizes; (void)n_in; (void)out_size;
  const float* x    = (const float*)d_in[0];
  const float* Wq   = (const float*)d_in[1];
  const float* Wk   = (const float*)d_in[2];
  const float* Wv   = (const float*)d_in[3];
  const float* Wp   = (const float*)d_in[4];
  const float* bp   = (const float*)d_in[5];
  const float* ln1g = (const float*)d_in[6];
  const float* ln1b = (const float*)d_in[7];
  const float* ln2g = (const float*)d_in[8];
  const float* ln2b = (const float*)d_in[9];
  const float* W1   = (const float*)d_in[10];
  const float* b1   = (const float*)d_in[11];
  const float* W2   = (const float*)d_in[12];
  const float* b2   = (const float*)d_in[13];
  float* out = (float*)d_out;

  unsigned nk1_0, nk1_1, nk2_0, nk2_1;
  tf2x32(0u, 42u, 0u, 0u, nk1_0, nk1_1);
  tf2x32(0u, 42u, 0u, 1u, nk2_0, nk2_1);

  cudaFuncSetAttribute(block_kernel, cudaFuncAttributeMaxDynamicSharedMemorySize, MEGA_SMEM);

  prep_kernel <<<324, 256>>>(Wq, Wk, Wv, Wp, W1, W2);
  block_kernel<<<256, 768, MEGA_SMEM>>>(x, ln1g, ln1b, bp, b1, b2, ln2g, ln2b, out,
                                        nk1_0, nk1_1, nk2_0, nk2_1);
}